// round 2
// baseline (speedup 1.0000x reference)
#include <cuda_runtime.h>
#include <math.h>
#include <stdint.h>
#include <stddef.h>

#define B_   128
#define DIN_ 128
#define T_   1024
#define H_   512
#define G4H_ 2048
#define OUT_ 2

// ---------------- scratch (static device allocations; no cudaMalloc) ----------------
__device__ float g_xt [(size_t)B_ * T_ * DIN_];   // x transposed to [b][t][d]   (64 MB)
__device__ float g_xg [(size_t)B_ * T_ * G4H_];   // input-gate preacts [b][t][4H] (1.07 GB, reused by both layers)
__device__ float g_hs0[(size_t)B_ * T_ * H_ ];    // layer-0 hidden seq [b][t][H] (268 MB)
__device__ float g_hA [B_ * H_];
__device__ float g_hB [B_ * H_];
__device__ unsigned int g_bar_count;              // zero-init; returns to 0 after each barrier
__device__ unsigned int g_bar_gen;

// ---------------- software grid barrier (all CTAs co-resident by construction) ------
__device__ __forceinline__ void grid_barrier() {
    __syncthreads();
    if (threadIdx.x == 0) {
        __threadfence();
        unsigned int gen = *(volatile unsigned int*)&g_bar_gen;
        unsigned int arrived = atomicAdd(&g_bar_count, 1u);
        if (arrived == gridDim.x - 1) {
            g_bar_count = 0;
            __threadfence();
            atomicAdd(&g_bar_gen, 1u);
        } else {
            while (*(volatile unsigned int*)&g_bar_gen == gen) { }
        }
        __threadfence();
    }
    __syncthreads();
}

// ---------------- transpose x: (B, D, T) -> xt[b][t][d] -----------------------------
__global__ void transpose_kernel(const float* __restrict__ x) {
    __shared__ float tile[32][33];
    const int b  = blockIdx.z;
    const int t0 = blockIdx.x * 32;
    const int d0 = blockIdx.y * 32;
    const int tx = threadIdx.x, ty = threadIdx.y;
    #pragma unroll
    for (int i = 0; i < 4; ++i) {
        int d = d0 + ty + i * 8;
        tile[ty + i * 8][tx] = x[((size_t)b * DIN_ + d) * T_ + t0 + tx];
    }
    __syncthreads();
    #pragma unroll
    for (int i = 0; i < 4; ++i) {
        int t = t0 + ty + i * 8;
        g_xt[((size_t)b * T_ + t) * DIN_ + d0 + tx] = tile[tx][ty + i * 8];
    }
}

// ---------------- generic tiled GEMM: C[m][n] = b1[n]+b2[n] + sum_k A[m][k]*B[n][k] --
// A: MxK row-major, B: NxK row-major. Tile 64m x 64n, K-tile 32. 256 threads.
__global__ void gemm_bias_kernel(const float* __restrict__ A,
                                 const float* __restrict__ Bm,
                                 const float* __restrict__ bias1,
                                 const float* __restrict__ bias2,
                                 float* __restrict__ C,
                                 int M, int N, int K)
{
    __shared__ float sa[32][65];   // [k][m]
    __shared__ float sb[32][65];   // [k][n]
    const int tid = threadIdx.x;
    const int m0 = blockIdx.y * 64;
    const int n0 = blockIdx.x * 64;
    const int mq = tid & 15;       // 16 m-quads
    const int nq = tid >> 4;       // 16 n-quads
    const int lk = tid & 31;
    const int lr = tid >> 5;       // 0..7

    float acc[4][4];
    #pragma unroll
    for (int i = 0; i < 4; ++i)
        #pragma unroll
        for (int j = 0; j < 4; ++j) acc[i][j] = 0.f;

    for (int kt = 0; kt < K; kt += 32) {
        #pragma unroll
        for (int i = 0; i < 8; ++i) {
            int r = lr + i * 8;
            sa[lk][r] = A[(size_t)(m0 + r) * K + kt + lk];
            sb[lk][r] = Bm[(size_t)(n0 + r) * K + kt + lk];
        }
        __syncthreads();
        #pragma unroll
        for (int k = 0; k < 32; ++k) {
            float av[4], bv[4];
            #pragma unroll
            for (int i = 0; i < 4; ++i) av[i] = sa[k][4 * mq + i];
            #pragma unroll
            for (int j = 0; j < 4; ++j) bv[j] = sb[k][4 * nq + j];
            #pragma unroll
            for (int i = 0; i < 4; ++i)
                #pragma unroll
                for (int j = 0; j < 4; ++j)
                    acc[i][j] = fmaf(av[i], bv[j], acc[i][j]);
        }
        __syncthreads();
    }

    float bb[4];
    #pragma unroll
    for (int j = 0; j < 4; ++j) {
        int n = n0 + 4 * nq + j;
        bb[j] = bias1[n] + bias2[n];
    }
    #pragma unroll
    for (int i = 0; i < 4; ++i) {
        int m = m0 + 4 * mq + i;
        float4 o;
        o.x = acc[i][0] + bb[0];
        o.y = acc[i][1] + bb[1];
        o.z = acc[i][2] + bb[2];
        o.w = acc[i][3] + bb[3];
        *(float4*)&C[(size_t)m * N + n0 + 4 * nq] = o;
    }
}

// ---------------- persistent LSTM recurrence ----------------------------------------
// Grid: 128 CTAs = 4 b-tiles (32 b) x 32 j-tiles (16 j). 256 threads.
// Thread = (lane -> b_local, jg -> {j, j+8}); keeps c in registers.
__device__ __forceinline__ float sigm(float v) { return 1.f / (1.f + expf(-v)); }

__global__ void lstm_layer_kernel(const float* __restrict__ xg,   // [b][t][4H]
                                  const float* __restrict__ Whh,  // [4H][H]
                                  float* __restrict__ hA,
                                  float* __restrict__ hB,
                                  float* __restrict__ hs_out)     // [b][t][H] or null
{
    extern __shared__ float sh[];  // h_prev transposed: [k=512][bl pad 33]
    const int tid  = threadIdx.x;
    const int lane = tid & 31;
    const int jg   = tid >> 5;                 // 0..7
    const int b0   = (blockIdx.x & 3) * 32;
    const int j0   = (blockIdx.x >> 2) * 16;

    // init h(0) = 0
    for (int idx = blockIdx.x * blockDim.x + tid; idx < B_ * H_;
         idx += gridDim.x * blockDim.x)
        hA[idx] = 0.f;

    const int b  = b0 + lane;
    const int j1 = j0 + jg;
    const int j2 = j0 + jg + 8;

    const float4* wr[2][4];
    #pragma unroll
    for (int g = 0; g < 4; ++g) {
        wr[0][g] = (const float4*)(Whh + (size_t)(g * H_ + j1) * H_);
        wr[1][g] = (const float4*)(Whh + (size_t)(g * H_ + j2) * H_);
    }
    const float* xgb = xg + (size_t)b * T_ * G4H_;

    float c0 = 0.f, c1 = 0.f;
    grid_barrier();

    for (int t = 0; t < T_; ++t) {
        const float* hr = (t & 1) ? hB : hA;
        float*       hw = (t & 1) ? hA : hB;

        // stage h_prev[b0..b0+31][:] into smem, transposed with pad
        const float4* hr4 = (const float4*)hr;
        for (int idx = tid; idx < 32 * (H_ / 4); idx += 256) {
            int bl = idx >> 7;           // 0..31
            int k4 = idx & 127;          // 0..127
            float4 v = hr4[(size_t)(b0 + bl) * (H_ / 4) + k4];
            int k = k4 * 4;
            sh[(k + 0) * 33 + bl] = v.x;
            sh[(k + 1) * 33 + bl] = v.y;
            sh[(k + 2) * 33 + bl] = v.z;
            sh[(k + 3) * 33 + bl] = v.w;
        }
        __syncthreads();

        const float* xgp = xgb + (size_t)t * G4H_;
        float a[2][4];
        #pragma unroll
        for (int g = 0; g < 4; ++g) {
            a[0][g] = xgp[g * H_ + j1];
            a[1][g] = xgp[g * H_ + j2];
        }

        #pragma unroll 2
        for (int k4 = 0; k4 < H_ / 4; ++k4) {
            const int k = k4 * 4;
            const float h0v = sh[(k + 0) * 33 + lane];
            const float h1v = sh[(k + 1) * 33 + lane];
            const float h2v = sh[(k + 2) * 33 + lane];
            const float h3v = sh[(k + 3) * 33 + lane];
            #pragma unroll
            for (int cidx = 0; cidx < 2; ++cidx) {
                #pragma unroll
                for (int g = 0; g < 4; ++g) {
                    float4 w = __ldg(&wr[cidx][g][k4]);
                    float s = a[cidx][g];
                    s = fmaf(w.x, h0v, s);
                    s = fmaf(w.y, h1v, s);
                    s = fmaf(w.z, h2v, s);
                    s = fmaf(w.w, h3v, s);
                    a[cidx][g] = s;
                }
            }
        }

        // cell 1
        {
            float ii = sigm(a[0][0]);
            float ff = sigm(a[0][1]);
            float gg = tanhf(a[0][2]);
            float oo = sigm(a[0][3]);
            c0 = ff * c0 + ii * gg;
            float hv = oo * tanhf(c0);
            hw[(size_t)b * H_ + j1] = hv;
            if (hs_out) hs_out[((size_t)b * T_ + t) * H_ + j1] = hv;
        }
        // cell 2
        {
            float ii = sigm(a[1][0]);
            float ff = sigm(a[1][1]);
            float gg = tanhf(a[1][2]);
            float oo = sigm(a[1][3]);
            c1 = ff * c1 + ii * gg;
            float hv = oo * tanhf(c1);
            hw[(size_t)b * H_ + j2] = hv;
            if (hs_out) hs_out[((size_t)b * T_ + t) * H_ + j2] = hv;
        }

        grid_barrier();   // publishes hw, also fences smem reuse
    }
}

// ---------------- fc head -----------------------------------------------------------
__global__ void fc_kernel(const float* __restrict__ h,
                          const float* __restrict__ W,
                          const float* __restrict__ bias,
                          float* __restrict__ out)
{
    int tid = threadIdx.x;       // 256 threads: (b, o)
    int b = tid >> 1, o = tid & 1;
    float s = bias[o];
    const float* hp = h + (size_t)b * H_;
    const float* wp = W + (size_t)o * H_;
    for (int k = 0; k < H_; ++k) s = fmaf(hp[k], wp[k], s);
    out[b * OUT_ + o] = s;
}

// ---------------- launch -------------------------------------------------------------
extern "C" void kernel_launch(void* const* d_in, const int* in_sizes, int n_in,
                              void* d_out, int out_size)
{
    const float* x    = (const float*)d_in[0];
    const float* Wih0 = (const float*)d_in[1];
    const float* Whh0 = (const float*)d_in[2];
    const float* bih0 = (const float*)d_in[3];
    const float* bhh0 = (const float*)d_in[4];
    const float* Wih1 = (const float*)d_in[5];
    const float* Whh1 = (const float*)d_in[6];
    const float* bih1 = (const float*)d_in[7];
    const float* bhh1 = (const float*)d_in[8];
    const float* fcW  = (const float*)d_in[9];
    const float* fcb  = (const float*)d_in[10];
    float* out = (float*)d_out;

    float *xt, *xg, *hs0, *hA, *hB;
    cudaGetSymbolAddress((void**)&xt,  g_xt);
    cudaGetSymbolAddress((void**)&xg,  g_xg);
    cudaGetSymbolAddress((void**)&hs0, g_hs0);
    cudaGetSymbolAddress((void**)&hA,  g_hA);
    cudaGetSymbolAddress((void**)&hB,  g_hB);

    const int LSTM_SMEM = H_ * 33 * (int)sizeof(float);  // 67584
    cudaFuncSetAttribute(lstm_layer_kernel,
                         cudaFuncAttributeMaxDynamicSharedMemorySize, LSTM_SMEM);

    // 1) transpose x -> xt[b][t][d]
    transpose_kernel<<<dim3(T_ / 32, DIN_ / 32, B_), dim3(32, 8)>>>(x);

    // 2) xg0 = xt @ Wih0^T + (bih0+bhh0)   (M = B*T, N = 4H, K = DIN)
    gemm_bias_kernel<<<dim3(G4H_ / 64, (B_ * T_) / 64), 256>>>(
        xt, Wih0, bih0, bhh0, xg, B_ * T_, G4H_, DIN_);

    // 3) layer-0 recurrence (writes hs0)
    lstm_layer_kernel<<<128, 256, LSTM_SMEM>>>(xg, Whh0, hA, hB, hs0);

    // 4) xg1 = hs0 @ Wih1^T + (bih1+bhh1)  (M = B*T, N = 4H, K = H)
    gemm_bias_kernel<<<dim3(G4H_ / 64, (B_ * T_) / 64), 256>>>(
        hs0, Wih1, bih1, bhh1, xg, B_ * T_, G4H_, H_);

    // 5) layer-1 recurrence (final h lands in hA since T is even)
    lstm_layer_kernel<<<128, 256, LSTM_SMEM>>>(xg, Whh1, hA, hB, (float*)0);

    // 6) fc head
    fc_kernel<<<1, 256>>>(hA, fcW, fcb, out);
}

// round 3
// speedup vs baseline: 2.5995x; 2.5995x over previous
#include <cuda_runtime.h>
#include <math.h>
#include <stdint.h>
#include <stddef.h>

#define B_   128
#define DIN_ 128
#define T_   1024
#define H_   512
#define G4H_ 2048
#define OUT_ 2

typedef unsigned long long ull;

// ---------------- scratch (static device allocations; no cudaMalloc) ----------------
__device__ float g_xt [(size_t)T_ * B_ * DIN_];   // x transposed to [t][b][d]
__device__ float g_xg [(size_t)T_ * G4H_ * B_];   // gate preacts [t][n][b] (1.07 GB)
__device__ float g_hs0[(size_t)T_ * B_ * H_ ];    // layer-0 hidden seq [t][b][k]
__device__ float g_hA [B_ * H_];                  // h ping-pong, layout [b][j]
__device__ float g_hB [B_ * H_];
__device__ unsigned int g_bar[4 * 32];            // 4 group barriers, 128B apart

// ---------------- packed fp32x2 FMA (2x FFMA throughput on sm_103a) -----------------
__device__ __forceinline__ void fma2(ull& acc, ull a, ull b) {
    asm("fma.rn.f32x2 %0, %1, %2, %0;" : "+l"(acc) : "l"(a), "l"(b));
}

// ---------------- per-b-group barrier (32 CTAs, all co-resident) --------------------
__device__ __forceinline__ void group_barrier(unsigned int* bar) {
    __syncthreads();
    if (threadIdx.x == 0) {
        __threadfence();
        unsigned int gen = ((volatile unsigned int*)bar)[1];
        if (atomicAdd(&bar[0], 1u) == 31u) {
            bar[0] = 0;
            __threadfence();
            atomicAdd(&bar[1], 1u);
        } else {
            while (((volatile unsigned int*)bar)[1] == gen) { }
        }
        __threadfence();
    }
    __syncthreads();
}

// ---------------- transpose x: (B, D, T) -> xt[t][b][d] -----------------------------
__global__ void transpose_kernel(const float* __restrict__ x) {
    __shared__ float tile[32][33];
    const int b  = blockIdx.z;
    const int t0 = blockIdx.x * 32;
    const int d0 = blockIdx.y * 32;
    const int tx = threadIdx.x, ty = threadIdx.y;
    #pragma unroll
    for (int i = 0; i < 4; ++i) {
        int d = d0 + ty + i * 8;
        tile[ty + i * 8][tx] = x[((size_t)b * DIN_ + d) * T_ + t0 + tx];
    }
    __syncthreads();
    #pragma unroll
    for (int i = 0; i < 4; ++i) {
        int t = t0 + ty + i * 8;
        g_xt[((size_t)t * B_ + b) * DIN_ + d0 + tx] = tile[tx][ty + i * 8];
    }
}

// ---------------- tiled GEMM: out[t][n][b] = b1[n]+b2[n] + sum_k A[m][k]*B[n][k] ----
// A: MxK row-major with m = t*128 + b. B: NxK row-major. Tile 64m x 64n, K-tile 32.
__global__ void gemm_bias_kernel(const float* __restrict__ A,
                                 const float* __restrict__ Bm,
                                 const float* __restrict__ bias1,
                                 const float* __restrict__ bias2,
                                 float* __restrict__ C,
                                 int M, int N, int K)
{
    __shared__ float sa[32][65];   // [k][m]
    __shared__ float sb[32][65];   // [k][n]
    const int tid = threadIdx.x;
    const int m0 = blockIdx.y * 64;
    const int n0 = blockIdx.x * 64;
    const int mq = tid & 15;
    const int nq = tid >> 4;
    const int lk = tid & 31;
    const int lr = tid >> 5;

    float acc[4][4];
    #pragma unroll
    for (int i = 0; i < 4; ++i)
        #pragma unroll
        for (int j = 0; j < 4; ++j) acc[i][j] = 0.f;

    for (int kt = 0; kt < K; kt += 32) {
        #pragma unroll
        for (int i = 0; i < 8; ++i) {
            int r = lr + i * 8;
            sa[lk][r] = A[(size_t)(m0 + r) * K + kt + lk];
            sb[lk][r] = Bm[(size_t)(n0 + r) * K + kt + lk];
        }
        __syncthreads();
        #pragma unroll
        for (int k = 0; k < 32; ++k) {
            float av[4], bv[4];
            #pragma unroll
            for (int i = 0; i < 4; ++i) av[i] = sa[k][4 * mq + i];
            #pragma unroll
            for (int j = 0; j < 4; ++j) bv[j] = sb[k][4 * nq + j];
            #pragma unroll
            for (int i = 0; i < 4; ++i)
                #pragma unroll
                for (int j = 0; j < 4; ++j)
                    acc[i][j] = fmaf(av[i], bv[j], acc[i][j]);
        }
        __syncthreads();
    }

    // epilogue: write [t][n][b] with b contiguous (m-tile covers a single t)
    const int tt = m0 >> 7;
    const int bb = (m0 & 127) + 4 * mq;
    #pragma unroll
    for (int j = 0; j < 4; ++j) {
        int n = n0 + 4 * nq + j;
        float bv = bias1[n] + bias2[n];
        float4 o;
        o.x = acc[0][j] + bv;
        o.y = acc[1][j] + bv;
        o.z = acc[2][j] + bv;
        o.w = acc[3][j] + bv;
        *(float4*)&C[((size_t)tt * G4H_ + n) * B_ + bb] = o;
    }
}

// ---------------- persistent LSTM recurrence ----------------------------------------
// 128 CTAs x 256 thr = 4 b-groups (32 b) x 32 j-tiles (16 j).
// Whh slice (64 rows x 512) resident in SMEM; h_prev staged in SMEM [bl][516];
// c kept in registers; per-step sync = 32-CTA group barrier.
__device__ __forceinline__ float sigm(float v) { return 1.f / (1.f + expf(-v)); }

__global__ void __launch_bounds__(256, 1)
lstm_layer_kernel(const float* __restrict__ xg,   // [t][n][b]
                  const float* __restrict__ Whh,  // [4H][H]
                  float* __restrict__ hA,
                  float* __restrict__ hB,
                  float* __restrict__ hs_out)     // [t][b][k] or null
{
    extern __shared__ float smem[];
    float* wsm = smem;                // 64 * 512 floats  (128 KB)
    float* hsm = smem + 64 * 512;     // 32 * 516 floats  (64.5 KB)

    const int tid  = threadIdx.x;
    const int lane = tid & 31;
    const int jg   = tid >> 5;                 // warp 0..7
    const int grp  = blockIdx.x & 3;           // b-group
    const int jt   = blockIdx.x >> 2;          // 0..31
    const int b0   = grp * 32;
    const int j0   = jt * 16;
    unsigned int* bar = g_bar + grp * 32;

    // ---- preload Whh slice into SMEM: row sr = warp*8 + (c*4+g) ----
    #pragma unroll
    for (int i = 0; i < 32; ++i) {
        int idx = tid + i * 256;          // float4 index, 0..8191
        int sr  = idx >> 7;               // 0..63
        int k4  = idx & 127;
        int r   = sr & 7;
        int jgs = sr >> 3;
        int c   = r >> 2, g = r & 3;
        int j   = j0 + jgs + 8 * c;
        *(float4*)&wsm[sr * 512 + 4 * k4] =
            *(const float4*)&Whh[(size_t)(g * H_ + j) * H_ + 4 * k4];
    }

    // ---- zero this CTA's h(0) slice ----
    if (tid < 128) {
        int r = tid >> 2, c4 = tid & 3;
        *(float4*)&hA[(size_t)(b0 + r) * H_ + j0 + 4 * c4] = make_float4(0.f, 0.f, 0.f, 0.f);
    }
    group_barrier(bar);

    const int j1 = j0 + jg;
    const int j2 = j0 + jg + 8;
    const ulonglong2* wp = (const ulonglong2*)(wsm + jg * 8 * 512);  // 8 rows x 128 ull2

    float c0 = 0.f, c1 = 0.f;

    for (int t = 0; t < T_; ++t) {
        const float* hr = (t & 1) ? hB : hA;   // h_{t-1}
        float*       hw = (t & 1) ? hA : hB;   // h_t

        // stage h_prev[b0..b0+31][:] into smem [bl][516] (vector, conflict-free)
        const float4* hr4 = (const float4*)hr;
        #pragma unroll
        for (int i = 0; i < 16; ++i) {
            int idx = tid + i * 256;
            int bl = idx >> 7, k4 = idx & 127;
            *(float4*)&hsm[bl * 516 + 4 * k4] = hr4[(size_t)(b0 + bl) * 128 + k4];
        }
        __syncthreads();

        // designated CTAs dump h_{t-1} -> hs0[t-1][b][k] (coalesced, global->global)
        if (hs_out && jt == 0 && t >= 1) {
            #pragma unroll
            for (int i = 0; i < 16; ++i) {
                int idx = tid + i * 256;
                int bl = idx >> 7, k4 = idx & 127;
                *(float4*)&hs_out[((size_t)(t - 1) * B_ + b0 + bl) * H_ + 4 * k4] =
                    hr4[(size_t)(b0 + bl) * 128 + k4];
            }
        }

        // prefetch gate preacts (coalesced over b)
        float xv[8];
        #pragma unroll
        for (int r = 0; r < 8; ++r) {
            int c = r >> 2, g = r & 3;
            int j = c ? j2 : j1;
            xv[r] = xg[((size_t)t * G4H_ + g * H_ + j) * B_ + b0 + lane];
        }

        // matvec: 8 gate rows x 512 k, packed f32x2 FMA
        ull acc2[8];
        #pragma unroll
        for (int r = 0; r < 8; ++r) acc2[r] = 0ull;

        const ulonglong2* hp = (const ulonglong2*)(hsm + lane * 516);
        #pragma unroll 4
        for (int k4 = 0; k4 < 128; ++k4) {
            ulonglong2 h2 = hp[k4];
            #pragma unroll
            for (int r = 0; r < 8; ++r) {
                ulonglong2 w2 = wp[r * 128 + k4];
                fma2(acc2[r], w2.x, h2.x);
                fma2(acc2[r], w2.y, h2.y);
            }
        }

        float a[8];
        #pragma unroll
        for (int r = 0; r < 8; ++r) {
            float lo = __uint_as_float((unsigned)(acc2[r] & 0xffffffffull));
            float hi = __uint_as_float((unsigned)(acc2[r] >> 32));
            a[r] = lo + hi + xv[r];
        }

        const int b = b0 + lane;
        {
            float ii = sigm(a[0]), ff = sigm(a[1]), gg = tanhf(a[2]), oo = sigm(a[3]);
            c0 = ff * c0 + ii * gg;
            hw[(size_t)b * H_ + j1] = oo * tanhf(c0);
        }
        {
            float ii = sigm(a[4]), ff = sigm(a[5]), gg = tanhf(a[6]), oo = sigm(a[7]);
            c1 = ff * c1 + ii * gg;
            hw[(size_t)b * H_ + j2] = oo * tanhf(c1);
        }

        group_barrier(bar);   // publish h_t to the group; protects hsm reuse
    }

    // final dump: hs0[T-1] from h_{T-1} (lives in hA since T is even)
    if (hs_out && jt == 0) {
        const float4* hr4 = (const float4*)hA;
        #pragma unroll
        for (int i = 0; i < 16; ++i) {
            int idx = tid + i * 256;
            int bl = idx >> 7, k4 = idx & 127;
            *(float4*)&hs_out[((size_t)(T_ - 1) * B_ + b0 + bl) * H_ + 4 * k4] =
                hr4[(size_t)(b0 + bl) * 128 + k4];
        }
    }
}

// ---------------- fc head -----------------------------------------------------------
__global__ void fc_kernel(const float* __restrict__ h,
                          const float* __restrict__ W,
                          const float* __restrict__ bias,
                          float* __restrict__ out)
{
    int tid = threadIdx.x;       // 256 threads: (b, o)
    int b = tid >> 1, o = tid & 1;
    float s = bias[o];
    const float* hp = h + (size_t)b * H_;
    const float* wp = W + (size_t)o * H_;
    for (int k = 0; k < H_; ++k) s = fmaf(hp[k], wp[k], s);
    out[b * OUT_ + o] = s;
}

// ---------------- launch -------------------------------------------------------------
extern "C" void kernel_launch(void* const* d_in, const int* in_sizes, int n_in,
                              void* d_out, int out_size)
{
    const float* x    = (const float*)d_in[0];
    const float* Wih0 = (const float*)d_in[1];
    const float* Whh0 = (const float*)d_in[2];
    const float* bih0 = (const float*)d_in[3];
    const float* bhh0 = (const float*)d_in[4];
    const float* Wih1 = (const float*)d_in[5];
    const float* Whh1 = (const float*)d_in[6];
    const float* bih1 = (const float*)d_in[7];
    const float* bhh1 = (const float*)d_in[8];
    const float* fcW  = (const float*)d_in[9];
    const float* fcb  = (const float*)d_in[10];
    float* out = (float*)d_out;

    float *xt, *xg, *hs0, *hA, *hB;
    cudaGetSymbolAddress((void**)&xt,  g_xt);
    cudaGetSymbolAddress((void**)&xg,  g_xg);
    cudaGetSymbolAddress((void**)&hs0, g_hs0);
    cudaGetSymbolAddress((void**)&hA,  g_hA);
    cudaGetSymbolAddress((void**)&hB,  g_hB);

    const int LSTM_SMEM = (64 * 512 + 32 * 516) * (int)sizeof(float);  // 197120 B
    cudaFuncSetAttribute(lstm_layer_kernel,
                         cudaFuncAttributeMaxDynamicSharedMemorySize, LSTM_SMEM);

    // 1) transpose x -> xt[t][b][d]
    transpose_kernel<<<dim3(T_ / 32, DIN_ / 32, B_), dim3(32, 8)>>>(x);

    // 2) xg0[t][n][b] = xt @ Wih0^T + (bih0+bhh0)
    gemm_bias_kernel<<<dim3(G4H_ / 64, (B_ * T_) / 64), 256>>>(
        xt, Wih0, bih0, bhh0, xg, B_ * T_, G4H_, DIN_);

    // 3) layer-0 recurrence (writes hs0[t][b][k])
    lstm_layer_kernel<<<128, 256, LSTM_SMEM>>>(xg, Whh0, hA, hB, hs0);

    // 4) xg1[t][n][b] = hs0 @ Wih1^T + (bih1+bhh1)
    gemm_bias_kernel<<<dim3(G4H_ / 64, (B_ * T_) / 64), 256>>>(
        hs0, Wih1, bih1, bhh1, xg, B_ * T_, G4H_, H_);

    // 5) layer-1 recurrence (final h lands in hA since T is even)
    lstm_layer_kernel<<<128, 256, LSTM_SMEM>>>(xg, Whh1, hA, hB, (float*)0);

    // 6) fc head
    fc_kernel<<<1, 256>>>(hA, fcW, fcb, out);
}

// round 5
// speedup vs baseline: 3.0998x; 1.1925x over previous
#include <cuda_runtime.h>
#include <cuda_bf16.h>
#include <math.h>
#include <stdint.h>
#include <stddef.h>

#define B_   128
#define DIN_ 128
#define T_   1024
#define H_   512
#define G4H_ 2048
#define OUT_ 2

typedef unsigned long long ull;

// ---------------- scratch (static device allocations; no cudaMalloc) ----------------
__device__ __nv_bfloat16 g_xth [(size_t)T_ * B_ * DIN_];  // x transposed, bf16 hi
__device__ __nv_bfloat16 g_xtl [(size_t)T_ * B_ * DIN_];  // bf16 lo residual
__device__ __nv_bfloat16 g_w0h [(size_t)G4H_ * DIN_];
__device__ __nv_bfloat16 g_w0l [(size_t)G4H_ * DIN_];
__device__ __nv_bfloat16 g_w1h [(size_t)G4H_ * H_];
__device__ __nv_bfloat16 g_w1l [(size_t)G4H_ * H_];
__device__ __nv_bfloat16 g_hs0h[(size_t)T_ * B_ * H_];    // layer-0 hidden, bf16 hi
__device__ __nv_bfloat16 g_hs0l[(size_t)T_ * B_ * H_];
__device__ float g_xg [(size_t)T_ * G4H_ * B_];           // gate preacts [t][n][b]
__device__ float g_hA [B_ * H_];
__device__ float g_hB [B_ * H_];
__device__ unsigned int g_bar[4 * 32];

// ---------------- small helpers -----------------------------------------------------
__device__ __forceinline__ void fma2(ull& acc, ull a, ull b) {
    asm("fma.rn.f32x2 %0, %1, %2, %0;" : "+l"(acc) : "l"(a), "l"(b));
}
__device__ __forceinline__ void bfsplit(float v, unsigned short& h, unsigned short& l) {
    __nv_bfloat16 hb = __float2bfloat16(v);
    float r = v - __bfloat162float(hb);
    __nv_bfloat16 lb = __float2bfloat16(r);
    h = __bfloat16_as_ushort(hb);
    l = __bfloat16_as_ushort(lb);
}
__device__ __forceinline__ uint32_t smem_u32(const void* p) {
    uint32_t a;
    asm("{ .reg .u64 t; cvta.to.shared.u64 t, %1; cvt.u32.u64 %0, t; }" : "=r"(a) : "l"(p));
    return a;
}
#define SWZ128(o) ((o) ^ (((o) >> 3) & 0x70))

__device__ __forceinline__ void ldsm_x4(uint32_t* r, uint32_t addr) {
    asm volatile("ldmatrix.sync.aligned.m8n8.x4.shared.b16 {%0,%1,%2,%3}, [%4];"
        : "=r"(r[0]), "=r"(r[1]), "=r"(r[2]), "=r"(r[3]) : "r"(addr));
}
__device__ __forceinline__ void mma16816(float* d, const uint32_t* a, const uint32_t* b) {
    asm volatile("mma.sync.aligned.m16n8k16.row.col.f32.bf16.bf16.f32 "
        "{%0,%1,%2,%3}, {%4,%5,%6,%7}, {%8,%9}, {%0,%1,%2,%3};"
        : "+f"(d[0]), "+f"(d[1]), "+f"(d[2]), "+f"(d[3])
        : "r"(a[0]), "r"(a[1]), "r"(a[2]), "r"(a[3]), "r"(b[0]), "r"(b[1]));
}
#define CPASYNC16(dst, src) \
    asm volatile("cp.async.cg.shared.global [%0], [%1], 16;" :: "r"(dst), "l"(src))
#define CPCOMMIT() asm volatile("cp.async.commit_group;" ::: "memory")
#define CPWAIT0()  asm volatile("cp.async.wait_group 0;" ::: "memory")
#define CPWAIT1()  asm volatile("cp.async.wait_group 1;" ::: "memory")

// ---------------- per-b-group barrier (32 CTAs) --------------------------------------
__device__ __forceinline__ void group_barrier(unsigned int* bar) {
    __syncthreads();
    if (threadIdx.x == 0) {
        __threadfence();
        unsigned int gen = ((volatile unsigned int*)bar)[1];
        if (atomicAdd(&bar[0], 1u) == 31u) {
            bar[0] = 0;
            __threadfence();
            atomicAdd(&bar[1], 1u);
        } else {
            while (((volatile unsigned int*)bar)[1] == gen) { }
        }
        __threadfence();
    }
    __syncthreads();
}

// ---------------- transpose x: (B, D, T) -> xt[t][b][d] as bf16 hi/lo ----------------
__global__ void transpose_kernel(const float* __restrict__ x) {
    __shared__ float tile[32][33];
    const int b  = blockIdx.z;
    const int t0 = blockIdx.x * 32;
    const int d0 = blockIdx.y * 32;
    const int tx = threadIdx.x, ty = threadIdx.y;
    #pragma unroll
    for (int i = 0; i < 4; ++i) {
        int d = d0 + ty + i * 8;
        tile[ty + i * 8][tx] = x[((size_t)b * DIN_ + d) * T_ + t0 + tx];
    }
    __syncthreads();
    #pragma unroll
    for (int i = 0; i < 4; ++i) {
        int t = t0 + ty + i * 8;
        float v = tile[tx][ty + i * 8];
        unsigned short h, l;
        bfsplit(v, h, l);
        size_t idx = ((size_t)t * B_ + b) * DIN_ + d0 + tx;
        g_xth[idx] = __ushort_as_bfloat16(h);
        g_xtl[idx] = __ushort_as_bfloat16(l);
    }
}

// ---------------- weight split fp32 -> bf16 hi/lo ------------------------------------
__global__ void wsplit_kernel(const float* __restrict__ w,
                              __nv_bfloat16* __restrict__ wh,
                              __nv_bfloat16* __restrict__ wl, int n) {
    int i = blockIdx.x * blockDim.x + threadIdx.x;
    if (i < n) {
        unsigned short h, l;
        bfsplit(w[i], h, l);
        wh[i] = __ushort_as_bfloat16(h);
        wl[i] = __ushort_as_bfloat16(l);
    }
}

// ---------------- mma.sync split-bf16 GEMM -------------------------------------------
// D[128m x 128n] per CTA, m-tile = one t, rows = b. A: MxK bf16 hi/lo row-major
// (m = t*128+b). B: NxK bf16 hi/lo row-major. Out: xg[t][n][b] fp32 + bias.
// smem: 2 stages x 4 tiles (Ah,Al,Bh,Bl) x 128 rows x 128B (SW128 swizzled) = 128 KB.
#define TILE_BYTES  16384
#define STAGE_BYTES (4 * TILE_BYTES)
#define GSM_TOTAL   (2 * STAGE_BYTES)

__global__ void __launch_bounds__(256, 1)
gemm_mma_kernel(const __nv_bfloat16* __restrict__ Ah, const __nv_bfloat16* __restrict__ Al,
                const __nv_bfloat16* __restrict__ Bh, const __nv_bfloat16* __restrict__ Bl,
                const float* __restrict__ bias1, const float* __restrict__ bias2,
                float* __restrict__ C, int K)
{
    extern __shared__ char smem[];
    const uint32_t sb = smem_u32(smem);
    const int tid  = threadIdx.x;
    const int lane = tid & 31;
    const int warp = tid >> 5;
    const int tile_t = blockIdx.y;
    const int n0blk  = blockIdx.x * 128;
    const int m_off = (warp & 3) * 32;
    const int n_off = (warp >> 2) * 64;

    const __nv_bfloat16* gsrc[4] = {
        Ah + (size_t)tile_t * 128 * K, Al + (size_t)tile_t * 128 * K,
        Bh + (size_t)n0blk * K,        Bl + (size_t)n0blk * K };

    // stage issue: 4096 x 16B chunks, 16 per thread
    auto issue_stage = [&](int buf, int kc) {
        #pragma unroll
        for (int i = 0; i < 16; ++i) {
            int id  = tid + i * 256;
            int tl  = id >> 10;
            int rem = id & 1023;
            int row = rem >> 3;
            int ch  = rem & 7;
            const __nv_bfloat16* src = gsrc[tl] + (size_t)row * K + kc * 64 + ch * 8;
            uint32_t dst = sb + buf * STAGE_BYTES + tl * TILE_BYTES
                         + SWZ128((uint32_t)(row * 128 + ch * 16));
            CPASYNC16(dst, src);
        }
        CPCOMMIT();
    };

    float acc[2][8][4];
    #pragma unroll
    for (int mf = 0; mf < 2; ++mf)
        #pragma unroll
        for (int nf = 0; nf < 8; ++nf)
            #pragma unroll
            for (int r = 0; r < 4; ++r) acc[mf][nf][r] = 0.f;

    const int nkc = K >> 6;
    issue_stage(0, 0);
    issue_stage(1, 1);   // nkc >= 2 always (K=128 or 512)

    // precomputed lane addressing offsets (within a tile)
    const int a_row_base = (lane & 7) + ((lane >> 3) & 1) * 8;   // + m_off + mf*16
    const int a_kh       = (lane >> 4) * 16;                     // byte
    const int b_row_base = (lane & 7) + ((lane >> 4) & 1) * 8;   // + n_off + bf*16
    const int b_kh       = ((lane >> 3) & 1) * 16;               // byte

    for (int kc = 0; kc < nkc; ++kc) {
        if (kc + 1 < nkc) { CPWAIT1(); } else { CPWAIT0(); }
        __syncthreads();

        const uint32_t st = sb + (kc & 1) * STAGE_BYTES;
        #pragma unroll
        for (int ks = 0; ks < 4; ++ks) {
            uint32_t ah[2][4], al[2][4], bh[16], bl[16];
            #pragma unroll
            for (int mf = 0; mf < 2; ++mf) {
                uint32_t off = SWZ128((uint32_t)((m_off + mf * 16 + a_row_base) * 128
                                                 + ks * 32 + a_kh));
                ldsm_x4(ah[mf], st + 0 * TILE_BYTES + off);
                ldsm_x4(al[mf], st + 1 * TILE_BYTES + off);
            }
            #pragma unroll
            for (int bf = 0; bf < 4; ++bf) {
                uint32_t off = SWZ128((uint32_t)((n_off + bf * 16 + b_row_base) * 128
                                                 + ks * 32 + b_kh));
                ldsm_x4(bh + bf * 4, st + 2 * TILE_BYTES + off);
                ldsm_x4(bl + bf * 4, st + 3 * TILE_BYTES + off);
            }
            #pragma unroll
            for (int mf = 0; mf < 2; ++mf)
                #pragma unroll
                for (int nf = 0; nf < 8; ++nf) {
                    mma16816(acc[mf][nf], ah[mf], bh + nf * 2);
                    mma16816(acc[mf][nf], ah[mf], bl + nf * 2);
                    mma16816(acc[mf][nf], al[mf], bh + nf * 2);
                }
        }
        __syncthreads();
        if (kc + 2 < nkc) issue_stage(kc & 1, kc + 2);
    }

    // epilogue: D row = b, col = n ; write xg[t][n][b] (+bias)
    #pragma unroll
    for (int nf = 0; nf < 8; ++nf) {
        int n = n0blk + n_off + nf * 8 + 2 * (lane & 3);
        float bv0 = __ldg(&bias1[n])     + __ldg(&bias2[n]);
        float bv1 = __ldg(&bias1[n + 1]) + __ldg(&bias2[n + 1]);
        #pragma unroll
        for (int mf = 0; mf < 2; ++mf) {
            int b = m_off + mf * 16 + (lane >> 2);
            float* c0 = &C[((size_t)tile_t * G4H_ + n) * B_ + b];
            c0[0]       = acc[mf][nf][0] + bv0;
            c0[B_]      = acc[mf][nf][1] + bv1;
            c0[8]       = acc[mf][nf][2] + bv0;
            c0[B_ + 8]  = acc[mf][nf][3] + bv1;
        }
    }
}

// ---------------- persistent LSTM recurrence ------------------------------------------
__device__ __forceinline__ float sigm(float v) { return 1.f / (1.f + expf(-v)); }

__global__ void __launch_bounds__(256, 1)
lstm_layer_kernel(const float* __restrict__ xg,   // [t][n][b]
                  const float* __restrict__ Whh,  // [4H][H]
                  float* __restrict__ hA,
                  float* __restrict__ hB,
                  __nv_bfloat16* __restrict__ hs_h,  // [t][b][k] bf16 hi, or null
                  __nv_bfloat16* __restrict__ hs_l)
{
    extern __shared__ float fsm[];
    float* wsm = fsm;                // 64 * 512 floats (128 KB)
    float* hsm = fsm + 64 * 512;     // 32 * 516 floats

    const int tid  = threadIdx.x;
    const int lane = tid & 31;
    const int jg   = tid >> 5;
    const int grp  = blockIdx.x & 3;
    const int jt   = blockIdx.x >> 2;
    const int b0   = grp * 32;
    const int j0   = jt * 16;
    unsigned int* bar = g_bar + grp * 32;

    #pragma unroll
    for (int i = 0; i < 32; ++i) {
        int idx = tid + i * 256;
        int sr  = idx >> 7;
        int k4  = idx & 127;
        int r   = sr & 7;
        int jgs = sr >> 3;
        int c   = r >> 2, g = r & 3;
        int j   = j0 + jgs + 8 * c;
        *(float4*)&wsm[sr * 512 + 4 * k4] =
            *(const float4*)&Whh[(size_t)(g * H_ + j) * H_ + 4 * k4];
    }
    if (tid < 128) {
        int r = tid >> 2, c4 = tid & 3;
        *(float4*)&hA[(size_t)(b0 + r) * H_ + j0 + 4 * c4] = make_float4(0.f, 0.f, 0.f, 0.f);
    }
    group_barrier(bar);

    const int j1 = j0 + jg;
    const int j2 = j0 + jg + 8;
    const ulonglong2* wp = (const ulonglong2*)(wsm + jg * 8 * 512);

    float c0 = 0.f, c1 = 0.f;

    for (int t = 0; t < T_; ++t) {
        const float* hr = (t & 1) ? hB : hA;
        float*       hw = (t & 1) ? hA : hB;

        const float4* hr4 = (const float4*)hr;
        #pragma unroll
        for (int i = 0; i < 16; ++i) {
            int idx = tid + i * 256;
            int bl = idx >> 7, k4 = idx & 127;
            *(float4*)&hsm[bl * 516 + 4 * k4] = hr4[(size_t)(b0 + bl) * 128 + k4];
        }
        __syncthreads();

        if (hs_h && jt == 0 && t >= 1) {
            #pragma unroll
            for (int i = 0; i < 16; ++i) {
                int idx = tid + i * 256;
                int bl = idx >> 7, k4 = idx & 127;
                float4 v = hr4[(size_t)(b0 + bl) * 128 + k4];
                unsigned short h0,l0,h1,l1,h2,l2,h3,l3;
                bfsplit(v.x, h0, l0); bfsplit(v.y, h1, l1);
                bfsplit(v.z, h2, l2); bfsplit(v.w, h3, l3);
                size_t o = ((size_t)(t - 1) * B_ + b0 + bl) * H_ + 4 * k4;
                uint2 uh, ul;
                uh.x = (uint32_t)h0 | ((uint32_t)h1 << 16);
                uh.y = (uint32_t)h2 | ((uint32_t)h3 << 16);
                ul.x = (uint32_t)l0 | ((uint32_t)l1 << 16);
                ul.y = (uint32_t)l2 | ((uint32_t)l3 << 16);
                *(uint2*)&hs_h[o] = uh;
                *(uint2*)&hs_l[o] = ul;
            }
        }

        float xv[8];
        #pragma unroll
        for (int r = 0; r < 8; ++r) {
            int c = r >> 2, g = r & 3;
            int j = c ? j2 : j1;
            xv[r] = xg[((size_t)t * G4H_ + g * H_ + j) * B_ + b0 + lane];
        }

        ull acc2[8];
        #pragma unroll
        for (int r = 0; r < 8; ++r) acc2[r] = 0ull;

        const ulonglong2* hp = (const ulonglong2*)(hsm + lane * 516);
        #pragma unroll 4
        for (int k4 = 0; k4 < 128; ++k4) {
            ulonglong2 h2 = hp[k4];
            #pragma unroll
            for (int r = 0; r < 8; ++r) {
                ulonglong2 w2 = wp[r * 128 + k4];
                fma2(acc2[r], w2.x, h2.x);
                fma2(acc2[r], w2.y, h2.y);
            }
        }

        float a[8];
        #pragma unroll
        for (int r = 0; r < 8; ++r) {
            float lo = __uint_as_float((unsigned)(acc2[r] & 0xffffffffull));
            float hi = __uint_as_float((unsigned)(acc2[r] >> 32));
            a[r] = lo + hi + xv[r];
        }

        const int b = b0 + lane;
        {
            float ii = sigm(a[0]), ff = sigm(a[1]), gg = tanhf(a[2]), oo = sigm(a[3]);
            c0 = ff * c0 + ii * gg;
            hw[(size_t)b * H_ + j1] = oo * tanhf(c0);
        }
        {
            float ii = sigm(a[4]), ff = sigm(a[5]), gg = tanhf(a[6]), oo = sigm(a[7]);
            c1 = ff * c1 + ii * gg;
            hw[(size_t)b * H_ + j2] = oo * tanhf(c1);
        }

        group_barrier(bar);
    }

    if (hs_h && jt == 0) {
        const float4* hr4 = (const float4*)hA;
        #pragma unroll
        for (int i = 0; i < 16; ++i) {
            int idx = tid + i * 256;
            int bl = idx >> 7, k4 = idx & 127;
            float4 v = hr4[(size_t)(b0 + bl) * 128 + k4];
            unsigned short h0,l0,h1,l1,h2,l2,h3,l3;
            bfsplit(v.x, h0, l0); bfsplit(v.y, h1, l1);
            bfsplit(v.z, h2, l2); bfsplit(v.w, h3, l3);
            size_t o = ((size_t)(T_ - 1) * B_ + b0 + bl) * H_ + 4 * k4;
            uint2 uh, ul;
            uh.x = (uint32_t)h0 | ((uint32_t)h1 << 16);
            uh.y = (uint32_t)h2 | ((uint32_t)h3 << 16);
            ul.x = (uint32_t)l0 | ((uint32_t)l1 << 16);
            ul.y = (uint32_t)l2 | ((uint32_t)l3 << 16);
            *(uint2*)&hs_h[o] = uh;
            *(uint2*)&hs_l[o] = ul;
        }
    }
}

// ---------------- fc head -----------------------------------------------------------
__global__ void fc_kernel(const float* __restrict__ h,
                          const float* __restrict__ W,
                          const float* __restrict__ bias,
                          float* __restrict__ out)
{
    int tid = threadIdx.x;
    int b = tid >> 1, o = tid & 1;
    float s = bias[o];
    const float* hp = h + (size_t)b * H_;
    const float* wp = W + (size_t)o * H_;
    for (int k = 0; k < H_; ++k) s = fmaf(hp[k], wp[k], s);
    out[b * OUT_ + o] = s;
}

// ---------------- launch -------------------------------------------------------------
extern "C" void kernel_launch(void* const* d_in, const int* in_sizes, int n_in,
                              void* d_out, int out_size)
{
    const float* x    = (const float*)d_in[0];
    const float* Wih0 = (const float*)d_in[1];
    const float* Whh0 = (const float*)d_in[2];
    const float* bih0 = (const float*)d_in[3];
    const float* bhh0 = (const float*)d_in[4];
    const float* Wih1 = (const float*)d_in[5];
    const float* Whh1 = (const float*)d_in[6];
    const float* bih1 = (const float*)d_in[7];
    const float* bhh1 = (const float*)d_in[8];
    const float* fcW  = (const float*)d_in[9];
    const float* fcb  = (const float*)d_in[10];
    float* out = (float*)d_out;

    float *xg, *hA, *hB;
    __nv_bfloat16 *xth, *xtl, *w0h, *w0l, *w1h, *w1l, *hs0h, *hs0l;
    cudaGetSymbolAddress((void**)&xg,   g_xg);
    cudaGetSymbolAddress((void**)&hA,   g_hA);
    cudaGetSymbolAddress((void**)&hB,   g_hB);
    cudaGetSymbolAddress((void**)&xth,  g_xth);
    cudaGetSymbolAddress((void**)&xtl,  g_xtl);
    cudaGetSymbolAddress((void**)&w0h,  g_w0h);
    cudaGetSymbolAddress((void**)&w0l,  g_w0l);
    cudaGetSymbolAddress((void**)&w1h,  g_w1h);
    cudaGetSymbolAddress((void**)&w1l,  g_w1l);
    cudaGetSymbolAddress((void**)&hs0h, g_hs0h);
    cudaGetSymbolAddress((void**)&hs0l, g_hs0l);

    const int LSTM_SMEM = (64 * 512 + 32 * 516) * (int)sizeof(float);
    cudaFuncSetAttribute(lstm_layer_kernel,
                         cudaFuncAttributeMaxDynamicSharedMemorySize, LSTM_SMEM);
    cudaFuncSetAttribute(gemm_mma_kernel,
                         cudaFuncAttributeMaxDynamicSharedMemorySize, GSM_TOTAL);

    // 1) transpose x -> bf16 hi/lo xt[t][b][d]
    transpose_kernel<<<dim3(T_ / 32, DIN_ / 32, B_), dim3(32, 8)>>>(x);

    // 2) split input weights
    wsplit_kernel<<<(G4H_ * DIN_ + 255) / 256, 256>>>(Wih0, w0h, w0l, G4H_ * DIN_);
    wsplit_kernel<<<(G4H_ * H_   + 255) / 256, 256>>>(Wih1, w1h, w1l, G4H_ * H_);

    // 3) xg0 = xt @ Wih0^T + bias (mma.sync split-bf16)
    gemm_mma_kernel<<<dim3(G4H_ / 128, T_), 256, GSM_TOTAL>>>(
        xth, xtl, w0h, w0l, bih0, bhh0, xg, DIN_);

    // 4) layer-0 recurrence (dumps hs0 as bf16 hi/lo)
    lstm_layer_kernel<<<128, 256, LSTM_SMEM>>>(xg, Whh0, hA, hB, hs0h, hs0l);

    // 5) xg1 = hs0 @ Wih1^T + bias
    gemm_mma_kernel<<<dim3(G4H_ / 128, T_), 256, GSM_TOTAL>>>(
        hs0h, hs0l, w1h, w1l, bih1, bhh1, xg, H_);

    // 6) layer-1 recurrence
    lstm_layer_kernel<<<128, 256, LSTM_SMEM>>>(xg, Whh1, hA, hB,
                                               (__nv_bfloat16*)0, (__nv_bfloat16*)0);

    // 7) fc head
    fc_kernel<<<1, 256>>>(hA, fcW, fcb, out);
}

// round 6
// speedup vs baseline: 6.2957x; 2.0310x over previous
#include <cuda_runtime.h>
#include <cuda_bf16.h>
#include <math.h>
#include <stdint.h>
#include <stddef.h>

#define B_   128
#define DIN_ 128
#define T_   1024
#define H_   512
#define G4H_ 2048
#define OUT_ 2

typedef unsigned long long ull;

// ---------------- scratch (static device allocations; no cudaMalloc) ----------------
__device__ __nv_bfloat16 g_xth [(size_t)T_ * B_ * DIN_];  // x transposed, bf16 hi
__device__ __nv_bfloat16 g_xtl [(size_t)T_ * B_ * DIN_];  // bf16 lo residual
__device__ __nv_bfloat16 g_w0h [(size_t)G4H_ * DIN_];
__device__ __nv_bfloat16 g_w0l [(size_t)G4H_ * DIN_];
__device__ __nv_bfloat16 g_w1h [(size_t)G4H_ * H_];
__device__ __nv_bfloat16 g_w1l [(size_t)G4H_ * H_];
__device__ __nv_bfloat16 g_wr0h[(size_t)G4H_ * H_];       // Whh0 bf16 hi/lo
__device__ __nv_bfloat16 g_wr0l[(size_t)G4H_ * H_];
__device__ __nv_bfloat16 g_wr1h[(size_t)G4H_ * H_];
__device__ __nv_bfloat16 g_wr1l[(size_t)G4H_ * H_];
__device__ __nv_bfloat16 g_hs0h[(size_t)T_ * B_ * H_];    // layer-0 hidden, bf16 hi
__device__ __nv_bfloat16 g_hs0l[(size_t)T_ * B_ * H_];
__device__ __nv_bfloat16 g_hh0 [B_ * H_];                 // h ping-pong, bf16 hi/lo
__device__ __nv_bfloat16 g_hl0 [B_ * H_];
__device__ __nv_bfloat16 g_hh1 [B_ * H_];
__device__ __nv_bfloat16 g_hl1 [B_ * H_];
__device__ float g_xg [(size_t)T_ * G4H_ * B_];           // gate preacts [t][n][b]
__device__ float g_hA [B_ * H_];                          // final h fp32 for fc
__device__ unsigned int g_bar[4 * 32];

// ---------------- small helpers -----------------------------------------------------
__device__ __forceinline__ void bfsplit(float v, unsigned short& h, unsigned short& l) {
    __nv_bfloat16 hb = __float2bfloat16(v);
    float r = v - __bfloat162float(hb);
    __nv_bfloat16 lb = __float2bfloat16(r);
    h = __bfloat16_as_ushort(hb);
    l = __bfloat16_as_ushort(lb);
}
__device__ __forceinline__ uint32_t smem_u32(const void* p) {
    uint32_t a;
    asm("{ .reg .u64 t; cvta.to.shared.u64 t, %1; cvt.u32.u64 %0, t; }" : "=r"(a) : "l"(p));
    return a;
}
#define SWZ128(o) ((o) ^ (((o) >> 3) & 0x70))

__device__ __forceinline__ void ldsm_x4(uint32_t* r, uint32_t addr) {
    asm volatile("ldmatrix.sync.aligned.m8n8.x4.shared.b16 {%0,%1,%2,%3}, [%4];"
        : "=r"(r[0]), "=r"(r[1]), "=r"(r[2]), "=r"(r[3]) : "r"(addr));
}
__device__ __forceinline__ void mma16816(float* d, const uint32_t* a, const uint32_t* b) {
    asm volatile("mma.sync.aligned.m16n8k16.row.col.f32.bf16.bf16.f32 "
        "{%0,%1,%2,%3}, {%4,%5,%6,%7}, {%8,%9}, {%0,%1,%2,%3};"
        : "+f"(d[0]), "+f"(d[1]), "+f"(d[2]), "+f"(d[3])
        : "r"(a[0]), "r"(a[1]), "r"(a[2]), "r"(a[3]), "r"(b[0]), "r"(b[1]));
}
#define CPASYNC16(dst, src) \
    asm volatile("cp.async.cg.shared.global [%0], [%1], 16;" :: "r"(dst), "l"(src))
#define CPCOMMIT() asm volatile("cp.async.commit_group;" ::: "memory")
#define CPWAIT0()  asm volatile("cp.async.wait_group 0;" ::: "memory")
#define CPWAIT1()  asm volatile("cp.async.wait_group 1;" ::: "memory")

// ---------------- per-b-group barrier (32 CTAs) --------------------------------------
__device__ __forceinline__ void group_barrier(unsigned int* bar) {
    __syncthreads();
    if (threadIdx.x == 0) {
        __threadfence();
        unsigned int gen = ((volatile unsigned int*)bar)[1];
        if (atomicAdd(&bar[0], 1u) == 31u) {
            bar[0] = 0;
            __threadfence();
            atomicAdd(&bar[1], 1u);
        } else {
            while (((volatile unsigned int*)bar)[1] == gen) { }
        }
        __threadfence();
    }
    __syncthreads();
}

// ---------------- transpose x: (B, D, T) -> xt[t][b][d] as bf16 hi/lo ----------------
__global__ void transpose_kernel(const float* __restrict__ x) {
    __shared__ float tile[32][33];
    const int b  = blockIdx.z;
    const int t0 = blockIdx.x * 32;
    const int d0 = blockIdx.y * 32;
    const int tx = threadIdx.x, ty = threadIdx.y;
    #pragma unroll
    for (int i = 0; i < 4; ++i) {
        int d = d0 + ty + i * 8;
        tile[ty + i * 8][tx] = x[((size_t)b * DIN_ + d) * T_ + t0 + tx];
    }
    __syncthreads();
    #pragma unroll
    for (int i = 0; i < 4; ++i) {
        int t = t0 + ty + i * 8;
        float v = tile[tx][ty + i * 8];
        unsigned short h, l;
        bfsplit(v, h, l);
        size_t idx = ((size_t)t * B_ + b) * DIN_ + d0 + tx;
        g_xth[idx] = __ushort_as_bfloat16(h);
        g_xtl[idx] = __ushort_as_bfloat16(l);
    }
}

// ---------------- weight split fp32 -> bf16 hi/lo ------------------------------------
__global__ void wsplit_kernel(const float* __restrict__ w,
                              __nv_bfloat16* __restrict__ wh,
                              __nv_bfloat16* __restrict__ wl, int n) {
    int i = blockIdx.x * blockDim.x + threadIdx.x;
    if (i < n) {
        unsigned short h, l;
        bfsplit(w[i], h, l);
        wh[i] = __ushort_as_bfloat16(h);
        wl[i] = __ushort_as_bfloat16(l);
    }
}

// ---------------- mma.sync split-bf16 GEMM (validated round 5) -----------------------
#define TILE_BYTES  16384
#define STAGE_BYTES (4 * TILE_BYTES)
#define GSM_TOTAL   (2 * STAGE_BYTES)

__global__ void __launch_bounds__(256, 1)
gemm_mma_kernel(const __nv_bfloat16* __restrict__ Ah, const __nv_bfloat16* __restrict__ Al,
                const __nv_bfloat16* __restrict__ Bh, const __nv_bfloat16* __restrict__ Bl,
                const float* __restrict__ bias1, const float* __restrict__ bias2,
                float* __restrict__ C, int K)
{
    extern __shared__ char smem[];
    const uint32_t sb = smem_u32(smem);
    const int tid  = threadIdx.x;
    const int lane = tid & 31;
    const int warp = tid >> 5;
    const int tile_t = blockIdx.y;
    const int n0blk  = blockIdx.x * 128;
    const int m_off = (warp & 3) * 32;
    const int n_off = (warp >> 2) * 64;

    const __nv_bfloat16* gsrc[4] = {
        Ah + (size_t)tile_t * 128 * K, Al + (size_t)tile_t * 128 * K,
        Bh + (size_t)n0blk * K,        Bl + (size_t)n0blk * K };

    auto issue_stage = [&](int buf, int kc) {
        #pragma unroll
        for (int i = 0; i < 16; ++i) {
            int id  = tid + i * 256;
            int tl  = id >> 10;
            int rem = id & 1023;
            int row = rem >> 3;
            int ch  = rem & 7;
            const __nv_bfloat16* src = gsrc[tl] + (size_t)row * K + kc * 64 + ch * 8;
            uint32_t dst = sb + buf * STAGE_BYTES + tl * TILE_BYTES
                         + SWZ128((uint32_t)(row * 128 + ch * 16));
            CPASYNC16(dst, src);
        }
        CPCOMMIT();
    };

    float acc[2][8][4];
    #pragma unroll
    for (int mf = 0; mf < 2; ++mf)
        #pragma unroll
        for (int nf = 0; nf < 8; ++nf)
            #pragma unroll
            for (int r = 0; r < 4; ++r) acc[mf][nf][r] = 0.f;

    const int nkc = K >> 6;
    issue_stage(0, 0);
    issue_stage(1, 1);

    const int a_row_base = (lane & 7) + ((lane >> 3) & 1) * 8;
    const int a_kh       = (lane >> 4) * 16;
    const int b_row_base = (lane & 7) + ((lane >> 4) & 1) * 8;
    const int b_kh       = ((lane >> 3) & 1) * 16;

    for (int kc = 0; kc < nkc; ++kc) {
        if (kc + 1 < nkc) { CPWAIT1(); } else { CPWAIT0(); }
        __syncthreads();

        const uint32_t st = sb + (kc & 1) * STAGE_BYTES;
        #pragma unroll
        for (int ks = 0; ks < 4; ++ks) {
            uint32_t ah[2][4], al[2][4], bh[16], bl[16];
            #pragma unroll
            for (int mf = 0; mf < 2; ++mf) {
                uint32_t off = SWZ128((uint32_t)((m_off + mf * 16 + a_row_base) * 128
                                                 + ks * 32 + a_kh));
                ldsm_x4(ah[mf], st + 0 * TILE_BYTES + off);
                ldsm_x4(al[mf], st + 1 * TILE_BYTES + off);
            }
            #pragma unroll
            for (int bf = 0; bf < 4; ++bf) {
                uint32_t off = SWZ128((uint32_t)((n_off + bf * 16 + b_row_base) * 128
                                                 + ks * 32 + b_kh));
                ldsm_x4(bh + bf * 4, st + 2 * TILE_BYTES + off);
                ldsm_x4(bl + bf * 4, st + 3 * TILE_BYTES + off);
            }
            #pragma unroll
            for (int mf = 0; mf < 2; ++mf)
                #pragma unroll
                for (int nf = 0; nf < 8; ++nf) {
                    mma16816(acc[mf][nf], ah[mf], bh + nf * 2);
                    mma16816(acc[mf][nf], ah[mf], bl + nf * 2);
                    mma16816(acc[mf][nf], al[mf], bh + nf * 2);
                }
        }
        __syncthreads();
        if (kc + 2 < nkc) issue_stage(kc & 1, kc + 2);
    }

    #pragma unroll
    for (int nf = 0; nf < 8; ++nf) {
        int n = n0blk + n_off + nf * 8 + 2 * (lane & 3);
        float bv0 = __ldg(&bias1[n])     + __ldg(&bias2[n]);
        float bv1 = __ldg(&bias1[n + 1]) + __ldg(&bias2[n + 1]);
        #pragma unroll
        for (int mf = 0; mf < 2; ++mf) {
            int b = m_off + mf * 16 + (lane >> 2);
            float* c0 = &C[((size_t)tile_t * G4H_ + n) * B_ + b];
            c0[0]       = acc[mf][nf][0] + bv0;
            c0[B_]      = acc[mf][nf][1] + bv1;
            c0[8]       = acc[mf][nf][2] + bv0;
            c0[B_ + 8]  = acc[mf][nf][3] + bv1;
        }
    }
}

// ---------------- persistent tensor-core LSTM recurrence -----------------------------
// 128 CTAs = 4 b-groups (32 b) x 32 j-tiles (16 j). 256 threads.
// Per step per CTA: gate preacts = Whh_slice[64 gate-rows x 512] @ h^T[512 x 32b]
// via split-bf16 mma.sync. Warp (mf = gate = wid&3, kh = k-half = wid>>2).
// Whh slice resident in SW128 smem (bf16 hi/lo, 128 KB). h exchanged via global bf16
// hi/lo ping-pong. Gate partials exchanged via padded smem; c-state in registers.
#define LSM_WHI  0
#define LSM_WLO  65536
#define LSM_HHI  131072
#define LSM_HLO  163840
#define LSM_RED  196608                 // 2 kh x 4 g x 16 m x 33 n x 4B = 16896
#define LSM_HOH  213504                 // 32 x 16 bf16 = 1024
#define LSM_HOL  214528
#define LSM_TOTAL 215552

__device__ __forceinline__ float sigm(float v) { return 1.f / (1.f + expf(-v)); }

__global__ void __launch_bounds__(256, 1)
lstm_mma_kernel(const float* __restrict__ xg,        // [t][n][b]
                const __nv_bfloat16* __restrict__ wrh,
                const __nv_bfloat16* __restrict__ wrl,
                __nv_bfloat16* __restrict__ hs_h,    // [t][b][k] or null
                __nv_bfloat16* __restrict__ hs_l,
                float* __restrict__ hfin)            // final fp32 h
{
    extern __shared__ char sm[];
    const uint32_t sb = smem_u32(sm);
    float* redf = (float*)(sm + LSM_RED);
    __nv_bfloat16* houth = (__nv_bfloat16*)(sm + LSM_HOH);
    __nv_bfloat16* houtl = (__nv_bfloat16*)(sm + LSM_HOL);

    const int tid  = threadIdx.x;
    const int lane = tid & 31;
    const int wid  = tid >> 5;
    const int grp  = blockIdx.x & 3;
    const int jt   = blockIdx.x >> 2;
    const int b0   = grp * 32;
    const int j0   = jt * 16;
    unsigned int* bar = g_bar + grp * 32;

    // ---- preload Whh slice (bf16 hi/lo) into chunked SW128 smem ----
    // smem row m = g*16 + jl (64 rows), 8 k-chunks of 128B each.
    #pragma unroll
    for (int i = 0; i < 32; ++i) {
        int id  = tid + i * 256;          // 0..8191 16B-chunks
        int hl  = id >> 12;
        int rem = id & 4095;
        int m   = rem >> 6;               // 0..63
        int ch  = rem & 63;               // 16B chunk in row
        int g = m >> 4, jl = m & 15;
        const __nv_bfloat16* src = (hl ? wrl : wrh)
            + ((size_t)(g * H_ + j0 + jl)) * H_ + ch * 8;
        int c = ch >> 3, cc = ch & 7;
        int off = (hl ? LSM_WLO : LSM_WHI) + c * 8192
                + (int)SWZ128((uint32_t)(m * 128 + cc * 16));
        *(uint4*)(sm + off) = *(const uint4*)src;
    }

    // ---- zero h ping buffer 0 (bf16 zeros are bit-zero) ----
    if (tid < 64) {
        ((uint4*)g_hh0)[blockIdx.x * 64 + tid] = make_uint4(0, 0, 0, 0);
        ((uint4*)g_hl0)[blockIdx.x * 64 + tid] = make_uint4(0, 0, 0, 0);
    }
    __threadfence();
    group_barrier(bar);

    // per-warp MMA constants
    const int mf = wid & 3;              // gate
    const int kh = wid >> 2;             // k-half
    const int a_row = mf * 16 + (lane & 7) + ((lane >> 3) & 1) * 8;
    const int a_kb  = (lane >> 4) * 16;
    const int b_row = (lane & 7) + ((lane >> 4) & 1) * 8;
    const int b_kb  = ((lane >> 3) & 1) * 16;

    // epilogue cell ownership: thread -> (b = eb, j = ej and ej+8)
    const int eb = tid & 31;
    const int ej = tid >> 5;
    float cst0 = 0.f, cst1 = 0.f;

    for (int t = 0; t < T_; ++t) {
        const __nv_bfloat16* rh = (t & 1) ? g_hh1 : g_hh0;
        const __nv_bfloat16* rl = (t & 1) ? g_hl1 : g_hl0;
        __nv_bfloat16* wh_ = (t & 1) ? g_hh0 : g_hh1;
        __nv_bfloat16* wl_ = (t & 1) ? g_hl0 : g_hl1;

        // ---- stage h_prev (32 b x 512 k, bf16 hi/lo) into SW128 smem via cp.async.cg
        #pragma unroll
        for (int i = 0; i < 16; ++i) {
            int id  = tid + i * 256;      // 0..4095
            int hl  = id >> 11;
            int rem = id & 2047;
            int bl  = rem >> 6;           // 0..31
            int ch  = rem & 63;
            const __nv_bfloat16* src = (hl ? rl : rh) + (size_t)(b0 + bl) * H_ + ch * 8;
            int c = ch >> 3, cc = ch & 7;
            uint32_t dst = sb + (hl ? LSM_HLO : LSM_HHI) + c * 4096
                         + SWZ128((uint32_t)(bl * 128 + cc * 16));
            CPASYNC16(dst, src);
        }
        CPCOMMIT();
        CPWAIT0();
        __syncthreads();

        // ---- MMA: acc[nf][4] over this warp's (gate, k-half)
        float acc[4][4];
        #pragma unroll
        for (int nf = 0; nf < 4; ++nf)
            #pragma unroll
            for (int q = 0; q < 4; ++q) acc[nf][q] = 0.f;

        #pragma unroll 4
        for (int kf = 0; kf < 16; ++kf) {
            int kfa = kh * 16 + kf;
            int c = kfa >> 2, ks = kfa & 3;
            uint32_t ah[4], al[4], bh[8], bl2[8];
            uint32_t aoff = sb + c * 8192
                          + SWZ128((uint32_t)(a_row * 128 + ks * 32 + a_kb));
            ldsm_x4(ah, aoff + LSM_WHI);
            ldsm_x4(al, aoff + LSM_WLO);
            #pragma unroll
            for (int nfp = 0; nfp < 2; ++nfp) {
                uint32_t boff = sb + c * 4096
                    + SWZ128((uint32_t)((nfp * 16 + b_row) * 128 + ks * 32 + b_kb));
                ldsm_x4(bh  + nfp * 4, boff + LSM_HHI);
                ldsm_x4(bl2 + nfp * 4, boff + LSM_HLO);
            }
            #pragma unroll
            for (int nf = 0; nf < 4; ++nf) {
                mma16816(acc[nf], ah, bh  + nf * 2);
                mma16816(acc[nf], ah, bl2 + nf * 2);
                mma16816(acc[nf], al, bh  + nf * 2);
            }
        }

        // ---- exchange partials via padded smem
        #pragma unroll
        for (int nf = 0; nf < 4; ++nf)
            #pragma unroll
            for (int q = 0; q < 4; ++q) {
                int m = (lane >> 2) + 8 * (q >> 1);
                int n = nf * 8 + 2 * (lane & 3) + (q & 1);
                redf[((kh * 4 + mf) * 16 + m) * 33 + n] = acc[nf][q];
            }
        __syncthreads();

        // ---- epilogue: 2 cells per thread, c-state in regs
        #pragma unroll
        for (int cell = 0; cell < 2; ++cell) {
            int jl = ej + cell * 8;
            float pre[4];
            #pragma unroll
            for (int g = 0; g < 4; ++g) {
                pre[g] = redf[(g * 16 + jl) * 33 + eb]
                       + redf[((4 + g) * 16 + jl) * 33 + eb]
                       + xg[((size_t)t * G4H_ + g * H_ + j0 + jl) * B_ + b0 + eb];
            }
            float ii = sigm(pre[0]), ff = sigm(pre[1]);
            float gg = tanhf(pre[2]), oo = sigm(pre[3]);
            float& cc = cell ? cst1 : cst0;
            cc = ff * cc + ii * gg;
            float hv = oo * tanhf(cc);
            unsigned short hh16, hl16;
            bfsplit(hv, hh16, hl16);
            houth[eb * 16 + jl] = __ushort_as_bfloat16(hh16);
            houtl[eb * 16 + jl] = __ushort_as_bfloat16(hl16);
            if (t == T_ - 1)
                hfin[(size_t)(b0 + eb) * H_ + j0 + jl] = hv;
        }
        __syncthreads();

        // ---- publish h_t (and hs0 dump) : 128 threads x 8B per buffer
        if (tid < 128) {
            int bl = tid >> 2, p = tid & 3;
            uint2 vh = *(uint2*)&houth[bl * 16 + p * 4];
            uint2 vl = *(uint2*)&houtl[bl * 16 + p * 4];
            size_t o = (size_t)(b0 + bl) * H_ + j0 + p * 4;
            *(uint2*)&wh_[o] = vh;
            *(uint2*)&wl_[o] = vl;
            if (hs_h) {
                size_t o2 = ((size_t)t * B_ + b0 + bl) * H_ + j0 + p * 4;
                *(uint2*)&hs_h[o2] = vh;
                *(uint2*)&hs_l[o2] = vl;
            }
        }
        __threadfence();
        group_barrier(bar);
    }
}

// ---------------- fc head -----------------------------------------------------------
__global__ void fc_kernel(const float* __restrict__ h,
                          const float* __restrict__ W,
                          const float* __restrict__ bias,
                          float* __restrict__ out)
{
    int tid = threadIdx.x;
    int b = tid >> 1, o = tid & 1;
    float s = bias[o];
    const float* hp = h + (size_t)b * H_;
    const float* wp = W + (size_t)o * H_;
    for (int k = 0; k < H_; ++k) s = fmaf(hp[k], wp[k], s);
    out[b * OUT_ + o] = s;
}

// ---------------- launch -------------------------------------------------------------
extern "C" void kernel_launch(void* const* d_in, const int* in_sizes, int n_in,
                              void* d_out, int out_size)
{
    const float* x    = (const float*)d_in[0];
    const float* Wih0 = (const float*)d_in[1];
    const float* Whh0 = (const float*)d_in[2];
    const float* bih0 = (const float*)d_in[3];
    const float* bhh0 = (const float*)d_in[4];
    const float* Wih1 = (const float*)d_in[5];
    const float* Whh1 = (const float*)d_in[6];
    const float* bih1 = (const float*)d_in[7];
    const float* bhh1 = (const float*)d_in[8];
    const float* fcW  = (const float*)d_in[9];
    const float* fcb  = (const float*)d_in[10];
    float* out = (float*)d_out;

    float *xg, *hA;
    __nv_bfloat16 *xth, *xtl, *w0h, *w0l, *w1h, *w1l, *hs0h, *hs0l;
    __nv_bfloat16 *wr0h, *wr0l, *wr1h, *wr1l;
    cudaGetSymbolAddress((void**)&xg,   g_xg);
    cudaGetSymbolAddress((void**)&hA,   g_hA);
    cudaGetSymbolAddress((void**)&xth,  g_xth);
    cudaGetSymbolAddress((void**)&xtl,  g_xtl);
    cudaGetSymbolAddress((void**)&w0h,  g_w0h);
    cudaGetSymbolAddress((void**)&w0l,  g_w0l);
    cudaGetSymbolAddress((void**)&w1h,  g_w1h);
    cudaGetSymbolAddress((void**)&w1l,  g_w1l);
    cudaGetSymbolAddress((void**)&wr0h, g_wr0h);
    cudaGetSymbolAddress((void**)&wr0l, g_wr0l);
    cudaGetSymbolAddress((void**)&wr1h, g_wr1h);
    cudaGetSymbolAddress((void**)&wr1l, g_wr1l);
    cudaGetSymbolAddress((void**)&hs0h, g_hs0h);
    cudaGetSymbolAddress((void**)&hs0l, g_hs0l);

    cudaFuncSetAttribute(lstm_mma_kernel,
                         cudaFuncAttributeMaxDynamicSharedMemorySize, LSM_TOTAL);
    cudaFuncSetAttribute(gemm_mma_kernel,
                         cudaFuncAttributeMaxDynamicSharedMemorySize, GSM_TOTAL);

    // 1) transpose x -> bf16 hi/lo xt[t][b][d]
    transpose_kernel<<<dim3(T_ / 32, DIN_ / 32, B_), dim3(32, 8)>>>(x);

    // 2) split weights (input + recurrent)
    wsplit_kernel<<<(G4H_ * DIN_ + 255) / 256, 256>>>(Wih0, w0h, w0l, G4H_ * DIN_);
    wsplit_kernel<<<(G4H_ * H_   + 255) / 256, 256>>>(Wih1, w1h, w1l, G4H_ * H_);
    wsplit_kernel<<<(G4H_ * H_   + 255) / 256, 256>>>(Whh0, wr0h, wr0l, G4H_ * H_);
    wsplit_kernel<<<(G4H_ * H_   + 255) / 256, 256>>>(Whh1, wr1h, wr1l, G4H_ * H_);

    // 3) xg0 = xt @ Wih0^T + bias
    gemm_mma_kernel<<<dim3(G4H_ / 128, T_), 256, GSM_TOTAL>>>(
        xth, xtl, w0h, w0l, bih0, bhh0, xg, DIN_);

    // 4) layer-0 recurrence (tensor cores; dumps hs0 bf16 hi/lo)
    lstm_mma_kernel<<<128, 256, LSM_TOTAL>>>(xg, wr0h, wr0l, hs0h, hs0l, hA);

    // 5) xg1 = hs0 @ Wih1^T + bias
    gemm_mma_kernel<<<dim3(G4H_ / 128, T_), 256, GSM_TOTAL>>>(
        hs0h, hs0l, w1h, w1l, bih1, bhh1, xg, H_);

    // 6) layer-1 recurrence (final fp32 h -> hA)
    lstm_mma_kernel<<<128, 256, LSM_TOTAL>>>(xg, wr1h, wr1l,
                                             (__nv_bfloat16*)0, (__nv_bfloat16*)0, hA);

    // 7) fc head
    fc_kernel<<<1, 256>>>(hA, fcW, fcb, out);
}

// round 7
// speedup vs baseline: 6.8259x; 1.0842x over previous
#include <cuda_runtime.h>
#include <cuda_bf16.h>
#include <math.h>
#include <stdint.h>
#include <stddef.h>

#define B_   128
#define DIN_ 128
#define T_   1024
#define H_   512
#define G4H_ 2048
#define OUT_ 2

typedef unsigned long long ull;

// ---------------- scratch (static device allocations; no cudaMalloc) ----------------
__device__ __nv_bfloat16 g_xth [(size_t)T_ * B_ * DIN_];  // x transposed, bf16 hi
__device__ __nv_bfloat16 g_xtl [(size_t)T_ * B_ * DIN_];  // bf16 lo residual
__device__ __nv_bfloat16 g_w0h [(size_t)G4H_ * DIN_];
__device__ __nv_bfloat16 g_w0l [(size_t)G4H_ * DIN_];
__device__ __nv_bfloat16 g_w1h [(size_t)G4H_ * H_];
__device__ __nv_bfloat16 g_w1l [(size_t)G4H_ * H_];
__device__ __nv_bfloat16 g_wr0h[(size_t)G4H_ * H_];       // Whh0 bf16 hi/lo
__device__ __nv_bfloat16 g_wr0l[(size_t)G4H_ * H_];
__device__ __nv_bfloat16 g_wr1h[(size_t)G4H_ * H_];
__device__ __nv_bfloat16 g_wr1l[(size_t)G4H_ * H_];
__device__ __nv_bfloat16 g_hs0h[(size_t)T_ * B_ * H_];    // layer-0 hidden, bf16 hi
__device__ __nv_bfloat16 g_hs0l[(size_t)T_ * B_ * H_];
__device__ __nv_bfloat16 g_hh0 [B_ * H_];                 // h ping-pong, bf16 hi/lo
__device__ __nv_bfloat16 g_hl0 [B_ * H_];
__device__ __nv_bfloat16 g_hh1 [B_ * H_];
__device__ __nv_bfloat16 g_hl1 [B_ * H_];
__device__ float g_xg [(size_t)T_ * G4H_ * B_];           // gate preacts [t][n][b]
__device__ float g_hA [B_ * H_];                          // final h fp32 for fc
__device__ unsigned int g_bar[4 * 32];

// ---------------- small helpers -----------------------------------------------------
__device__ __forceinline__ void bfsplit(float v, unsigned short& h, unsigned short& l) {
    __nv_bfloat16 hb = __float2bfloat16(v);
    float r = v - __bfloat162float(hb);
    __nv_bfloat16 lb = __float2bfloat16(r);
    h = __bfloat16_as_ushort(hb);
    l = __bfloat16_as_ushort(lb);
}
__device__ __forceinline__ uint32_t smem_u32(const void* p) {
    uint32_t a;
    asm("{ .reg .u64 t; cvta.to.shared.u64 t, %1; cvt.u32.u64 %0, t; }" : "=r"(a) : "l"(p));
    return a;
}
#define SWZ128(o) ((o) ^ (((o) >> 3) & 0x70))

__device__ __forceinline__ void ldsm_x4(uint32_t* r, uint32_t addr) {
    asm volatile("ldmatrix.sync.aligned.m8n8.x4.shared.b16 {%0,%1,%2,%3}, [%4];"
        : "=r"(r[0]), "=r"(r[1]), "=r"(r[2]), "=r"(r[3]) : "r"(addr));
}
__device__ __forceinline__ void mma16816(float* d, const uint32_t* a, const uint32_t* b) {
    asm volatile("mma.sync.aligned.m16n8k16.row.col.f32.bf16.bf16.f32 "
        "{%0,%1,%2,%3}, {%4,%5,%6,%7}, {%8,%9}, {%0,%1,%2,%3};"
        : "+f"(d[0]), "+f"(d[1]), "+f"(d[2]), "+f"(d[3])
        : "r"(a[0]), "r"(a[1]), "r"(a[2]), "r"(a[3]), "r"(b[0]), "r"(b[1]));
}
#define CPASYNC16(dst, src) \
    asm volatile("cp.async.cg.shared.global [%0], [%1], 16;" :: "r"(dst), "l"(src))
#define CPCOMMIT() asm volatile("cp.async.commit_group;" ::: "memory")
#define CPWAIT0()  asm volatile("cp.async.wait_group 0;" ::: "memory")
#define CPWAIT1()  asm volatile("cp.async.wait_group 1;" ::: "memory")

// ---------------- per-b-group barrier (32 CTAs) --------------------------------------
__device__ __forceinline__ void group_barrier(unsigned int* bar) {
    __syncthreads();
    if (threadIdx.x == 0) {
        __threadfence();
        unsigned int gen = ((volatile unsigned int*)bar)[1];
        if (atomicAdd(&bar[0], 1u) == 31u) {
            bar[0] = 0;
            __threadfence();
            atomicAdd(&bar[1], 1u);
        } else {
            while (((volatile unsigned int*)bar)[1] == gen) { }
        }
        __threadfence();
    }
    __syncthreads();
}

// ---------------- transpose x: (B, D, T) -> xt[t][b][d] as bf16 hi/lo ----------------
__global__ void transpose_kernel(const float* __restrict__ x) {
    __shared__ float tile[32][33];
    const int b  = blockIdx.z;
    const int t0 = blockIdx.x * 32;
    const int d0 = blockIdx.y * 32;
    const int tx = threadIdx.x, ty = threadIdx.y;
    #pragma unroll
    for (int i = 0; i < 4; ++i) {
        int d = d0 + ty + i * 8;
        tile[ty + i * 8][tx] = x[((size_t)b * DIN_ + d) * T_ + t0 + tx];
    }
    __syncthreads();
    #pragma unroll
    for (int i = 0; i < 4; ++i) {
        int t = t0 + ty + i * 8;
        float v = tile[tx][ty + i * 8];
        unsigned short h, l;
        bfsplit(v, h, l);
        size_t idx = ((size_t)t * B_ + b) * DIN_ + d0 + tx;
        g_xth[idx] = __ushort_as_bfloat16(h);
        g_xtl[idx] = __ushort_as_bfloat16(l);
    }
}

// ---------------- weight split fp32 -> bf16 hi/lo ------------------------------------
__global__ void wsplit_kernel(const float* __restrict__ w,
                              __nv_bfloat16* __restrict__ wh,
                              __nv_bfloat16* __restrict__ wl, int n) {
    int i = blockIdx.x * blockDim.x + threadIdx.x;
    if (i < n) {
        unsigned short h, l;
        bfsplit(w[i], h, l);
        wh[i] = __ushort_as_bfloat16(h);
        wl[i] = __ushort_as_bfloat16(l);
    }
}

// ---------------- mma.sync split-bf16 GEMM (validated round 5) -----------------------
#define TILE_BYTES  16384
#define STAGE_BYTES (4 * TILE_BYTES)
#define GSM_TOTAL   (2 * STAGE_BYTES)

__global__ void __launch_bounds__(256, 1)
gemm_mma_kernel(const __nv_bfloat16* __restrict__ Ah, const __nv_bfloat16* __restrict__ Al,
                const __nv_bfloat16* __restrict__ Bh, const __nv_bfloat16* __restrict__ Bl,
                const float* __restrict__ bias1, const float* __restrict__ bias2,
                float* __restrict__ C, int K)
{
    extern __shared__ char smem[];
    const uint32_t sb = smem_u32(smem);
    const int tid  = threadIdx.x;
    const int lane = tid & 31;
    const int warp = tid >> 5;
    const int tile_t = blockIdx.y;
    const int n0blk  = blockIdx.x * 128;
    const int m_off = (warp & 3) * 32;
    const int n_off = (warp >> 2) * 64;

    const __nv_bfloat16* gsrc[4] = {
        Ah + (size_t)tile_t * 128 * K, Al + (size_t)tile_t * 128 * K,
        Bh + (size_t)n0blk * K,        Bl + (size_t)n0blk * K };

    auto issue_stage = [&](int buf, int kc) {
        #pragma unroll
        for (int i = 0; i < 16; ++i) {
            int id  = tid + i * 256;
            int tl  = id >> 10;
            int rem = id & 1023;
            int row = rem >> 3;
            int ch  = rem & 7;
            const __nv_bfloat16* src = gsrc[tl] + (size_t)row * K + kc * 64 + ch * 8;
            uint32_t dst = sb + buf * STAGE_BYTES + tl * TILE_BYTES
                         + SWZ128((uint32_t)(row * 128 + ch * 16));
            CPASYNC16(dst, src);
        }
        CPCOMMIT();
    };

    float acc[2][8][4];
    #pragma unroll
    for (int mf = 0; mf < 2; ++mf)
        #pragma unroll
        for (int nf = 0; nf < 8; ++nf)
            #pragma unroll
            for (int r = 0; r < 4; ++r) acc[mf][nf][r] = 0.f;

    const int nkc = K >> 6;
    issue_stage(0, 0);
    issue_stage(1, 1);

    const int a_row_base = (lane & 7) + ((lane >> 3) & 1) * 8;
    const int a_kh       = (lane >> 4) * 16;
    const int b_row_base = (lane & 7) + ((lane >> 4) & 1) * 8;
    const int b_kh       = ((lane >> 3) & 1) * 16;

    for (int kc = 0; kc < nkc; ++kc) {
        if (kc + 1 < nkc) { CPWAIT1(); } else { CPWAIT0(); }
        __syncthreads();

        const uint32_t st = sb + (kc & 1) * STAGE_BYTES;
        #pragma unroll
        for (int ks = 0; ks < 4; ++ks) {
            uint32_t ah[2][4], al[2][4], bh[16], bl[16];
            #pragma unroll
            for (int mf = 0; mf < 2; ++mf) {
                uint32_t off = SWZ128((uint32_t)((m_off + mf * 16 + a_row_base) * 128
                                                 + ks * 32 + a_kh));
                ldsm_x4(ah[mf], st + 0 * TILE_BYTES + off);
                ldsm_x4(al[mf], st + 1 * TILE_BYTES + off);
            }
            #pragma unroll
            for (int bf = 0; bf < 4; ++bf) {
                uint32_t off = SWZ128((uint32_t)((n_off + bf * 16 + b_row_base) * 128
                                                 + ks * 32 + b_kh));
                ldsm_x4(bh + bf * 4, st + 2 * TILE_BYTES + off);
                ldsm_x4(bl + bf * 4, st + 3 * TILE_BYTES + off);
            }
            #pragma unroll
            for (int mf = 0; mf < 2; ++mf)
                #pragma unroll
                for (int nf = 0; nf < 8; ++nf) {
                    mma16816(acc[mf][nf], ah[mf], bh + nf * 2);
                    mma16816(acc[mf][nf], ah[mf], bl + nf * 2);
                    mma16816(acc[mf][nf], al[mf], bh + nf * 2);
                }
        }
        __syncthreads();
        if (kc + 2 < nkc) issue_stage(kc & 1, kc + 2);
    }

    #pragma unroll
    for (int nf = 0; nf < 8; ++nf) {
        int n = n0blk + n_off + nf * 8 + 2 * (lane & 3);
        float bv0 = __ldg(&bias1[n])     + __ldg(&bias2[n]);
        float bv1 = __ldg(&bias1[n + 1]) + __ldg(&bias2[n + 1]);
        #pragma unroll
        for (int mf = 0; mf < 2; ++mf) {
            int b = m_off + mf * 16 + (lane >> 2);
            float* c0 = &C[((size_t)tile_t * G4H_ + n) * B_ + b];
            c0[0]       = acc[mf][nf][0] + bv0;
            c0[B_]      = acc[mf][nf][1] + bv1;
            c0[8]       = acc[mf][nf][2] + bv0;
            c0[B_ + 8]  = acc[mf][nf][3] + bv1;
        }
    }
}

// ---------------- persistent tensor-core LSTM recurrence -----------------------------
// 128 CTAs = 4 b-groups (32 b) x 32 j-tiles (16 j). 256 threads.
// Warp = (gate mf = wid&3, k-half kh = wid>>2). Whh slice resident SW128 smem.
// xg preacts preloaded into kh=0 accumulators. Two-phase h staging (hi then lo).
#define LSM_WHI  0
#define LSM_WLO  65536
#define LSM_HHI  131072
#define LSM_HLO  163840
#define LSM_RED  196608                 // 2 kh x 4 g x 16 m x 33 n x 4B = 16896
#define LSM_HOH  213504                 // 32 x 16 bf16 = 1024
#define LSM_HOL  214528
#define LSM_TOTAL 215552

__device__ __forceinline__ float sigm_f(float v) {
    return __fdividef(1.f, 1.f + __expf(-v));
}
__device__ __forceinline__ float tanh_f(float v) {
    return 1.f - __fdividef(2.f, __expf(2.f * v) + 1.f);
}

__global__ void __launch_bounds__(256, 1)
lstm_mma_kernel(const float* __restrict__ xg,        // [t][n][b]
                const __nv_bfloat16* __restrict__ wrh,
                const __nv_bfloat16* __restrict__ wrl,
                __nv_bfloat16* __restrict__ hs_h,    // [t][b][k] or null
                __nv_bfloat16* __restrict__ hs_l,
                float* __restrict__ hfin)            // final fp32 h
{
    extern __shared__ char sm[];
    const uint32_t sb = smem_u32(sm);
    float* redf = (float*)(sm + LSM_RED);
    __nv_bfloat16* houth = (__nv_bfloat16*)(sm + LSM_HOH);
    __nv_bfloat16* houtl = (__nv_bfloat16*)(sm + LSM_HOL);

    const int tid  = threadIdx.x;
    const int lane = tid & 31;
    const int wid  = tid >> 5;
    const int grp  = blockIdx.x & 3;
    const int jt   = blockIdx.x >> 2;
    const int b0   = grp * 32;
    const int j0   = jt * 16;
    unsigned int* bar = g_bar + grp * 32;

    // ---- preload Whh slice (bf16 hi/lo) into chunked SW128 smem ----
    #pragma unroll
    for (int i = 0; i < 32; ++i) {
        int id  = tid + i * 256;          // 0..8191 16B-chunks
        int hl  = id >> 12;
        int rem = id & 4095;
        int m   = rem >> 6;               // 0..63
        int ch  = rem & 63;               // 16B chunk in row
        int g = m >> 4, jl = m & 15;
        const __nv_bfloat16* src = (hl ? wrl : wrh)
            + ((size_t)(g * H_ + j0 + jl)) * H_ + ch * 8;
        int c = ch >> 3, cc = ch & 7;
        int off = (hl ? LSM_WLO : LSM_WHI) + c * 8192
                + (int)SWZ128((uint32_t)(m * 128 + cc * 16));
        *(uint4*)(sm + off) = *(const uint4*)src;
    }

    // ---- zero h ping buffer 0 ----
    if (tid < 64) {
        ((uint4*)g_hh0)[blockIdx.x * 64 + tid] = make_uint4(0, 0, 0, 0);
        ((uint4*)g_hl0)[blockIdx.x * 64 + tid] = make_uint4(0, 0, 0, 0);
    }
    __threadfence();
    group_barrier(bar);

    // per-warp MMA constants
    const int mf = wid & 3;              // gate
    const int kh = wid >> 2;             // k-half
    const int a_row = mf * 16 + (lane & 7) + ((lane >> 3) & 1) * 8;
    const int a_kb  = (lane >> 4) * 16;
    const int b_row = (lane & 7) + ((lane >> 4) & 1) * 8;
    const int b_kb  = ((lane >> 3) & 1) * 16;

    // epilogue cell ownership
    const int eb = tid & 31;
    const int ej = tid >> 5;
    float cst0 = 0.f, cst1 = 0.f;

    for (int t = 0; t < T_; ++t) {
        const __nv_bfloat16* rh = (t & 1) ? g_hh1 : g_hh0;
        const __nv_bfloat16* rl = (t & 1) ? g_hl1 : g_hl0;
        __nv_bfloat16* wh_ = (t & 1) ? g_hh0 : g_hh1;
        __nv_bfloat16* wl_ = (t & 1) ? g_hl0 : g_hl1;

        // ---- early: init acc from xg (kh=0) — LDG latency hidden behind staging ----
        float acc[4][4];
        if (kh == 0) {
            #pragma unroll
            for (int nf = 0; nf < 4; ++nf)
                #pragma unroll
                for (int q = 0; q < 4; ++q) {
                    int jl = (lane >> 2) + 8 * (q >> 1);
                    int bn = nf * 8 + 2 * (lane & 3) + (q & 1);
                    acc[nf][q] = __ldg(&xg[((size_t)t * G4H_ + mf * H_ + j0 + jl) * B_
                                           + b0 + bn]);
                }
        } else {
            #pragma unroll
            for (int nf = 0; nf < 4; ++nf)
                #pragma unroll
                for (int q = 0; q < 4; ++q) acc[nf][q] = 0.f;
        }

        // ---- stage h_prev: hi group, then lo group (separate commits) ----
        #pragma unroll
        for (int i = 0; i < 8; ++i) {                // hi: ids 0..2047
            int id  = tid + i * 256;
            int bl  = (id & 2047) >> 6;
            int ch  = id & 63;
            const __nv_bfloat16* src = rh + (size_t)(b0 + bl) * H_ + ch * 8;
            int c = ch >> 3, cc = ch & 7;
            uint32_t dst = sb + LSM_HHI + c * 4096
                         + SWZ128((uint32_t)(bl * 128 + cc * 16));
            CPASYNC16(dst, src);
        }
        CPCOMMIT();
        #pragma unroll
        for (int i = 0; i < 8; ++i) {                // lo: ids 2048..4095
            int id  = tid + i * 256;
            int bl  = (id & 2047) >> 6;
            int ch  = id & 63;
            const __nv_bfloat16* src = rl + (size_t)(b0 + bl) * H_ + ch * 8;
            int c = ch >> 3, cc = ch & 7;
            uint32_t dst = sb + LSM_HLO + c * 4096
                         + SWZ128((uint32_t)(bl * 128 + cc * 16));
            CPASYNC16(dst, src);
        }
        CPCOMMIT();

        // ---- phase 1: Bh terms (Ah*Bh + Al*Bh) while lo still loads ----
        CPWAIT1();
        __syncthreads();
        #pragma unroll 4
        for (int kf = 0; kf < 16; ++kf) {
            int kfa = kh * 16 + kf;
            int c = kfa >> 2, ks = kfa & 3;
            uint32_t ah[4], al[4], bh[8];
            uint32_t aoff = sb + c * 8192
                          + SWZ128((uint32_t)(a_row * 128 + ks * 32 + a_kb));
            ldsm_x4(ah, aoff + LSM_WHI);
            ldsm_x4(al, aoff + LSM_WLO);
            #pragma unroll
            for (int nfp = 0; nfp < 2; ++nfp) {
                uint32_t boff = sb + LSM_HHI + c * 4096
                    + SWZ128((uint32_t)((nfp * 16 + b_row) * 128 + ks * 32 + b_kb));
                ldsm_x4(bh + nfp * 4, boff);
            }
            #pragma unroll
            for (int nf = 0; nf < 4; ++nf) {
                mma16816(acc[nf], ah, bh + nf * 2);
                mma16816(acc[nf], al, bh + nf * 2);
            }
        }

        // ---- phase 2: Bl term (Ah*Bl) ----
        CPWAIT0();
        __syncthreads();
        #pragma unroll 4
        for (int kf = 0; kf < 16; ++kf) {
            int kfa = kh * 16 + kf;
            int c = kfa >> 2, ks = kfa & 3;
            uint32_t ah[4], bl2[8];
            uint32_t aoff = sb + c * 8192
                          + SWZ128((uint32_t)(a_row * 128 + ks * 32 + a_kb));
            ldsm_x4(ah, aoff + LSM_WHI);
            #pragma unroll
            for (int nfp = 0; nfp < 2; ++nfp) {
                uint32_t boff = sb + LSM_HLO + c * 4096
                    + SWZ128((uint32_t)((nfp * 16 + b_row) * 128 + ks * 32 + b_kb));
                ldsm_x4(bl2 + nfp * 4, boff);
            }
            #pragma unroll
            for (int nf = 0; nf < 4; ++nf)
                mma16816(acc[nf], ah, bl2 + nf * 2);
        }

        // ---- exchange partials via padded smem ----
        #pragma unroll
        for (int nf = 0; nf < 4; ++nf)
            #pragma unroll
            for (int q = 0; q < 4; ++q) {
                int m = (lane >> 2) + 8 * (q >> 1);
                int n = nf * 8 + 2 * (lane & 3) + (q & 1);
                redf[((kh * 4 + mf) * 16 + m) * 33 + n] = acc[nf][q];
            }
        __syncthreads();

        // ---- epilogue: 2 cells per thread (xg already folded into kh=0 partials) ----
        #pragma unroll
        for (int cell = 0; cell < 2; ++cell) {
            int jl = ej + cell * 8;
            float pre[4];
            #pragma unroll
            for (int g = 0; g < 4; ++g) {
                pre[g] = redf[(g * 16 + jl) * 33 + eb]
                       + redf[((4 + g) * 16 + jl) * 33 + eb];
            }
            float ii = sigm_f(pre[0]), ff = sigm_f(pre[1]);
            float gg = tanh_f(pre[2]), oo = sigm_f(pre[3]);
            float& cc = cell ? cst1 : cst0;
            cc = ff * cc + ii * gg;
            float hv = oo * tanh_f(cc);
            unsigned short hh16, hl16;
            bfsplit(hv, hh16, hl16);
            houth[eb * 16 + jl] = __ushort_as_bfloat16(hh16);
            houtl[eb * 16 + jl] = __ushort_as_bfloat16(hl16);
            if (t == T_ - 1)
                hfin[(size_t)(b0 + eb) * H_ + j0 + jl] = hv;
        }
        __syncthreads();

        // ---- publish h_t to global ping-pong ----
        if (tid < 128) {
            int bl = tid >> 2, p = tid & 3;
            uint2 vh = *(uint2*)&houth[bl * 16 + p * 4];
            uint2 vl = *(uint2*)&houtl[bl * 16 + p * 4];
            size_t o = (size_t)(b0 + bl) * H_ + j0 + p * 4;
            *(uint2*)&wh_[o] = vh;
            *(uint2*)&wl_[o] = vl;
        }
        __threadfence();
        __syncthreads();

        // ---- group barrier with hs0 dump in the wait window ----
        unsigned int gen_ = 0;
        if (tid == 0) {
            gen_ = ((volatile unsigned int*)bar)[1];
            if (atomicAdd(&bar[0], 1u) == 31u) {
                bar[0] = 0;
                __threadfence();
                atomicAdd(&bar[1], 1u);
            }
        }
        if (hs_h && tid >= 128) {      // threads 128-255 dump while thread 0 waits
            int th = tid - 128;
            int bl = th >> 2, p = th & 3;
            uint2 vh = *(uint2*)&houth[bl * 16 + p * 4];
            uint2 vl = *(uint2*)&houtl[bl * 16 + p * 4];
            size_t o2 = ((size_t)t * B_ + b0 + bl) * H_ + j0 + p * 4;
            *(uint2*)&hs_h[o2] = vh;
            *(uint2*)&hs_l[o2] = vl;
        }
        if (tid == 0) {
            while (((volatile unsigned int*)bar)[1] == gen_) { }
            __threadfence();
        }
        __syncthreads();
    }
}

// ---------------- fc head -----------------------------------------------------------
__global__ void fc_kernel(const float* __restrict__ h,
                          const float* __restrict__ W,
                          const float* __restrict__ bias,
                          float* __restrict__ out)
{
    int tid = threadIdx.x;
    int b = tid >> 1, o = tid & 1;
    float s = bias[o];
    const float* hp = h + (size_t)b * H_;
    const float* wp = W + (size_t)o * H_;
    for (int k = 0; k < H_; ++k) s = fmaf(hp[k], wp[k], s);
    out[b * OUT_ + o] = s;
}

// ---------------- launch -------------------------------------------------------------
extern "C" void kernel_launch(void* const* d_in, const int* in_sizes, int n_in,
                              void* d_out, int out_size)
{
    const float* x    = (const float*)d_in[0];
    const float* Wih0 = (const float*)d_in[1];
    const float* Whh0 = (const float*)d_in[2];
    const float* bih0 = (const float*)d_in[3];
    const float* bhh0 = (const float*)d_in[4];
    const float* Wih1 = (const float*)d_in[5];
    const float* Whh1 = (const float*)d_in[6];
    const float* bih1 = (const float*)d_in[7];
    const float* bhh1 = (const float*)d_in[8];
    const float* fcW  = (const float*)d_in[9];
    const float* fcb  = (const float*)d_in[10];
    float* out = (float*)d_out;

    float *xg, *hA;
    __nv_bfloat16 *xth, *xtl, *w0h, *w0l, *w1h, *w1l, *hs0h, *hs0l;
    __nv_bfloat16 *wr0h, *wr0l, *wr1h, *wr1l;
    cudaGetSymbolAddress((void**)&xg,   g_xg);
    cudaGetSymbolAddress((void**)&hA,   g_hA);
    cudaGetSymbolAddress((void**)&xth,  g_xth);
    cudaGetSymbolAddress((void**)&xtl,  g_xtl);
    cudaGetSymbolAddress((void**)&w0h,  g_w0h);
    cudaGetSymbolAddress((void**)&w0l,  g_w0l);
    cudaGetSymbolAddress((void**)&w1h,  g_w1h);
    cudaGetSymbolAddress((void**)&w1l,  g_w1l);
    cudaGetSymbolAddress((void**)&wr0h, g_wr0h);
    cudaGetSymbolAddress((void**)&wr0l, g_wr0l);
    cudaGetSymbolAddress((void**)&wr1h, g_wr1h);
    cudaGetSymbolAddress((void**)&wr1l, g_wr1l);
    cudaGetSymbolAddress((void**)&hs0h, g_hs0h);
    cudaGetSymbolAddress((void**)&hs0l, g_hs0l);

    cudaFuncSetAttribute(lstm_mma_kernel,
                         cudaFuncAttributeMaxDynamicSharedMemorySize, LSM_TOTAL);
    cudaFuncSetAttribute(gemm_mma_kernel,
                         cudaFuncAttributeMaxDynamicSharedMemorySize, GSM_TOTAL);

    // 1) transpose x -> bf16 hi/lo xt[t][b][d]
    transpose_kernel<<<dim3(T_ / 32, DIN_ / 32, B_), dim3(32, 8)>>>(x);

    // 2) split weights (input + recurrent)
    wsplit_kernel<<<(G4H_ * DIN_ + 255) / 256, 256>>>(Wih0, w0h, w0l, G4H_ * DIN_);
    wsplit_kernel<<<(G4H_ * H_   + 255) / 256, 256>>>(Wih1, w1h, w1l, G4H_ * H_);
    wsplit_kernel<<<(G4H_ * H_   + 255) / 256, 256>>>(Whh0, wr0h, wr0l, G4H_ * H_);
    wsplit_kernel<<<(G4H_ * H_   + 255) / 256, 256>>>(Whh1, wr1h, wr1l, G4H_ * H_);

    // 3) xg0 = xt @ Wih0^T + bias
    gemm_mma_kernel<<<dim3(G4H_ / 128, T_), 256, GSM_TOTAL>>>(
        xth, xtl, w0h, w0l, bih0, bhh0, xg, DIN_);

    // 4) layer-0 recurrence (tensor cores; dumps hs0 bf16 hi/lo)
    lstm_mma_kernel<<<128, 256, LSM_TOTAL>>>(xg, wr0h, wr0l, hs0h, hs0l, hA);

    // 5) xg1 = hs0 @ Wih1^T + bias
    gemm_mma_kernel<<<dim3(G4H_ / 128, T_), 256, GSM_TOTAL>>>(
        hs0h, hs0l, w1h, w1l, bih1, bhh1, xg, H_);

    // 6) layer-1 recurrence (final fp32 h -> hA)
    lstm_mma_kernel<<<128, 256, LSM_TOTAL>>>(xg, wr1h, wr1l,
                                             (__nv_bfloat16*)0, (__nv_bfloat16*)0, hA);

    // 7) fc head
    fc_kernel<<<1, 256>>>(hA, fcW, fcb, out);
}

// round 8
// speedup vs baseline: 8.5008x; 1.2454x over previous
#include <cuda_runtime.h>
#include <cuda_fp16.h>
#include <math.h>
#include <stdint.h>
#include <stddef.h>

#define B_   128
#define DIN_ 128
#define T_   1024
#define H_   512
#define G4H_ 2048
#define OUT_ 2

// ---------------- scratch (static device allocations; no cudaMalloc) ----------------
__device__ __half g_xth [(size_t)T_ * B_ * DIN_];  // x transposed, fp16 hi
__device__ __half g_xtl [(size_t)T_ * B_ * DIN_];  // fp16 lo residual
__device__ __half g_w0h [(size_t)G4H_ * DIN_];
__device__ __half g_w0l [(size_t)G4H_ * DIN_];
__device__ __half g_w1h [(size_t)G4H_ * H_];
__device__ __half g_w1l [(size_t)G4H_ * H_];
__device__ __half g_wr0h[(size_t)G4H_ * H_];       // Whh0 fp16 hi/lo
__device__ __half g_wr0l[(size_t)G4H_ * H_];
__device__ __half g_wr1h[(size_t)G4H_ * H_];
__device__ __half g_wr1l[(size_t)G4H_ * H_];
__device__ __half g_hs0h[(size_t)T_ * B_ * H_];    // layer-0 hidden, fp16 hi
__device__ __half g_hs0l[(size_t)T_ * B_ * H_];
__device__ __half g_hh0 [B_ * H_];                 // h ping-pong, fp16 (hi only)
__device__ __half g_hh1 [B_ * H_];
__device__ float g_xg [(size_t)T_ * G4H_ * B_];    // gate preacts [t][n][b]
__device__ float g_hA [B_ * H_];                   // final h fp32 for fc
__device__ unsigned int g_bar[4 * 32];

// ---------------- small helpers -----------------------------------------------------
__device__ __forceinline__ void hsplit(float v, __half& h, __half& l) {
    h = __float2half(v);
    l = __float2half(v - __half2float(h));
}
__device__ __forceinline__ uint32_t smem_u32(const void* p) {
    uint32_t a;
    asm("{ .reg .u64 t; cvta.to.shared.u64 t, %1; cvt.u32.u64 %0, t; }" : "=r"(a) : "l"(p));
    return a;
}
#define SWZ128(o) ((o) ^ (((o) >> 3) & 0x70))

__device__ __forceinline__ void ldsm_x4(uint32_t* r, uint32_t addr) {
    asm volatile("ldmatrix.sync.aligned.m8n8.x4.shared.b16 {%0,%1,%2,%3}, [%4];"
        : "=r"(r[0]), "=r"(r[1]), "=r"(r[2]), "=r"(r[3]) : "r"(addr));
}
__device__ __forceinline__ void mma16816(float* d, const uint32_t* a, const uint32_t* b) {
    asm volatile("mma.sync.aligned.m16n8k16.row.col.f32.f16.f16.f32 "
        "{%0,%1,%2,%3}, {%4,%5,%6,%7}, {%8,%9}, {%0,%1,%2,%3};"
        : "+f"(d[0]), "+f"(d[1]), "+f"(d[2]), "+f"(d[3])
        : "r"(a[0]), "r"(a[1]), "r"(a[2]), "r"(a[3]), "r"(b[0]), "r"(b[1]));
}
#define CPASYNC16(dst, src) \
    asm volatile("cp.async.cg.shared.global [%0], [%1], 16;" :: "r"(dst), "l"(src))
#define CPCOMMIT() asm volatile("cp.async.commit_group;" ::: "memory")
#define CPWAIT0()  asm volatile("cp.async.wait_group 0;" ::: "memory")
#define CPWAIT1()  asm volatile("cp.async.wait_group 1;" ::: "memory")

// ---------------- per-b-group barrier (32 CTAs), release/acquire ---------------------
__device__ __forceinline__ void group_barrier(unsigned int* bar) {
    __syncthreads();
    if (threadIdx.x == 0) {
        unsigned int gen;
        asm volatile("ld.acquire.gpu.u32 %0, [%1];" : "=r"(gen) : "l"(bar + 1) : "memory");
        unsigned int arrived;
        asm volatile("atom.add.release.gpu.u32 %0, [%1], 1;"
                     : "=r"(arrived) : "l"(bar) : "memory");
        if (arrived == 31u) {
            asm volatile("st.relaxed.gpu.u32 [%0], 0;" :: "l"(bar) : "memory");
            asm volatile("red.add.release.gpu.u32 [%0], 1;" :: "l"(bar + 1) : "memory");
        } else {
            unsigned int g2;
            do {
                asm volatile("ld.acquire.gpu.u32 %0, [%1];"
                             : "=r"(g2) : "l"(bar + 1) : "memory");
            } while (g2 == gen);
        }
    }
    __syncthreads();
}

// ---------------- transpose x: (B, D, T) -> xt[t][b][d] as fp16 hi/lo ----------------
__global__ void transpose_kernel(const float* __restrict__ x) {
    __shared__ float tile[32][33];
    const int b  = blockIdx.z;
    const int t0 = blockIdx.x * 32;
    const int d0 = blockIdx.y * 32;
    const int tx = threadIdx.x, ty = threadIdx.y;
    #pragma unroll
    for (int i = 0; i < 4; ++i) {
        int d = d0 + ty + i * 8;
        tile[ty + i * 8][tx] = x[((size_t)b * DIN_ + d) * T_ + t0 + tx];
    }
    __syncthreads();
    #pragma unroll
    for (int i = 0; i < 4; ++i) {
        int t = t0 + ty + i * 8;
        float v = tile[tx][ty + i * 8];
        __half h, l;
        hsplit(v, h, l);
        size_t idx = ((size_t)t * B_ + b) * DIN_ + d0 + tx;
        g_xth[idx] = h;
        g_xtl[idx] = l;
    }
}

// ---------------- weight split fp32 -> fp16 hi/lo ------------------------------------
__global__ void wsplit_kernel(const float* __restrict__ w,
                              __half* __restrict__ wh,
                              __half* __restrict__ wl, int n) {
    int i = blockIdx.x * blockDim.x + threadIdx.x;
    if (i < n) {
        __half h, l;
        hsplit(w[i], h, l);
        wh[i] = h;
        wl[i] = l;
    }
}

// ---------------- mma.sync split-fp16 GEMM (3-product) -------------------------------
#define TILE_BYTES  16384
#define STAGE_BYTES (4 * TILE_BYTES)
#define GSM_TOTAL   (2 * STAGE_BYTES)

__global__ void __launch_bounds__(256, 1)
gemm_mma_kernel(const __half* __restrict__ Ah, const __half* __restrict__ Al,
                const __half* __restrict__ Bh, const __half* __restrict__ Bl,
                const float* __restrict__ bias1, const float* __restrict__ bias2,
                float* __restrict__ C, int K)
{
    extern __shared__ char smem[];
    const uint32_t sb = smem_u32(smem);
    const int tid  = threadIdx.x;
    const int lane = tid & 31;
    const int warp = tid >> 5;
    const int tile_t = blockIdx.y;
    const int n0blk  = blockIdx.x * 128;
    const int m_off = (warp & 3) * 32;
    const int n_off = (warp >> 2) * 64;

    const __half* gsrc[4] = {
        Ah + (size_t)tile_t * 128 * K, Al + (size_t)tile_t * 128 * K,
        Bh + (size_t)n0blk * K,        Bl + (size_t)n0blk * K };

    auto issue_stage = [&](int buf, int kc) {
        #pragma unroll
        for (int i = 0; i < 16; ++i) {
            int id  = tid + i * 256;
            int tl  = id >> 10;
            int rem = id & 1023;
            int row = rem >> 3;
            int ch  = rem & 7;
            const __half* src = gsrc[tl] + (size_t)row * K + kc * 64 + ch * 8;
            uint32_t dst = sb + buf * STAGE_BYTES + tl * TILE_BYTES
                         + SWZ128((uint32_t)(row * 128 + ch * 16));
            CPASYNC16(dst, src);
        }
        CPCOMMIT();
    };

    float acc[2][8][4];
    #pragma unroll
    for (int mf = 0; mf < 2; ++mf)
        #pragma unroll
        for (int nf = 0; nf < 8; ++nf)
            #pragma unroll
            for (int r = 0; r < 4; ++r) acc[mf][nf][r] = 0.f;

    const int nkc = K >> 6;
    issue_stage(0, 0);
    issue_stage(1, 1);

    const int a_row_base = (lane & 7) + ((lane >> 3) & 1) * 8;
    const int a_kh       = (lane >> 4) * 16;
    const int b_row_base = (lane & 7) + ((lane >> 4) & 1) * 8;
    const int b_kh       = ((lane >> 3) & 1) * 16;

    for (int kc = 0; kc < nkc; ++kc) {
        if (kc + 1 < nkc) { CPWAIT1(); } else { CPWAIT0(); }
        __syncthreads();

        const uint32_t st = sb + (kc & 1) * STAGE_BYTES;
        #pragma unroll
        for (int ks = 0; ks < 4; ++ks) {
            uint32_t ah[2][4], al[2][4], bh[16], bl[16];
            #pragma unroll
            for (int mf = 0; mf < 2; ++mf) {
                uint32_t off = SWZ128((uint32_t)((m_off + mf * 16 + a_row_base) * 128
                                                 + ks * 32 + a_kh));
                ldsm_x4(ah[mf], st + 0 * TILE_BYTES + off);
                ldsm_x4(al[mf], st + 1 * TILE_BYTES + off);
            }
            #pragma unroll
            for (int bf = 0; bf < 4; ++bf) {
                uint32_t off = SWZ128((uint32_t)((n_off + bf * 16 + b_row_base) * 128
                                                 + ks * 32 + b_kh));
                ldsm_x4(bh + bf * 4, st + 2 * TILE_BYTES + off);
                ldsm_x4(bl + bf * 4, st + 3 * TILE_BYTES + off);
            }
            #pragma unroll
            for (int mf = 0; mf < 2; ++mf)
                #pragma unroll
                for (int nf = 0; nf < 8; ++nf) {
                    mma16816(acc[mf][nf], ah[mf], bh + nf * 2);
                    mma16816(acc[mf][nf], ah[mf], bl + nf * 2);
                    mma16816(acc[mf][nf], al[mf], bh + nf * 2);
                }
        }
        __syncthreads();
        if (kc + 2 < nkc) issue_stage(kc & 1, kc + 2);
    }

    #pragma unroll
    for (int nf = 0; nf < 8; ++nf) {
        int n = n0blk + n_off + nf * 8 + 2 * (lane & 3);
        float bv0 = __ldg(&bias1[n])     + __ldg(&bias2[n]);
        float bv1 = __ldg(&bias1[n + 1]) + __ldg(&bias2[n + 1]);
        #pragma unroll
        for (int mf = 0; mf < 2; ++mf) {
            int b = m_off + mf * 16 + (lane >> 2);
            float* c0 = &C[((size_t)tile_t * G4H_ + n) * B_ + b];
            c0[0]       = acc[mf][nf][0] + bv0;
            c0[B_]      = acc[mf][nf][1] + bv1;
            c0[8]       = acc[mf][nf][2] + bv0;
            c0[B_ + 8]  = acc[mf][nf][3] + bv1;
        }
    }
}

// ---------------- persistent tensor-core LSTM recurrence (fp16 2-product) ------------
// 128 CTAs = 4 b-groups (32 b) x 32 j-tiles (16 j). 256 threads.
// Warp = (gate mf = wid&3, k-half kh = wid>>2). Whh fp16 hi/lo resident in smem.
// h exchanged as single fp16. xg preacts preloaded into kh=0 accumulators.
#define LSM_WHI  0
#define LSM_WLO  65536
#define LSM_HH   131072                 // 32 b x 512 k fp16 = 32 KB
#define LSM_RED  163840                 // 2 kh x 4 g x 16 m x 33 n x 4B = 16896
#define LSM_HOH  180736                 // 32 x 16 fp16 = 1 KB
#define LSM_HOL  181760
#define LSM_TOTAL 182784

__device__ __forceinline__ float sigm_f(float v) {
    return __fdividef(1.f, 1.f + __expf(-v));
}
__device__ __forceinline__ float tanh_f(float v) {
    return 1.f - __fdividef(2.f, __expf(2.f * v) + 1.f);
}

__global__ void __launch_bounds__(256, 1)
lstm_mma_kernel(const float* __restrict__ xg,        // [t][n][b]
                const __half* __restrict__ wrh,
                const __half* __restrict__ wrl,
                __half* __restrict__ hs_h,           // [t][b][k] or null
                __half* __restrict__ hs_l,
                float* __restrict__ hfin)            // final fp32 h
{
    extern __shared__ char sm[];
    const uint32_t sb = smem_u32(sm);
    float* redf = (float*)(sm + LSM_RED);
    __half* houth = (__half*)(sm + LSM_HOH);
    __half* houtl = (__half*)(sm + LSM_HOL);

    const int tid  = threadIdx.x;
    const int lane = tid & 31;
    const int wid  = tid >> 5;
    const int grp  = blockIdx.x & 3;
    const int jt   = blockIdx.x >> 2;
    const int b0   = grp * 32;
    const int j0   = jt * 16;
    unsigned int* bar = g_bar + grp * 32;

    // ---- preload Whh slice (fp16 hi/lo) into chunked SW128 smem ----
    #pragma unroll
    for (int i = 0; i < 32; ++i) {
        int id  = tid + i * 256;          // 0..8191 16B-chunks
        int hl  = id >> 12;
        int rem = id & 4095;
        int m   = rem >> 6;               // 0..63
        int ch  = rem & 63;
        int g = m >> 4, jl = m & 15;
        const __half* src = (hl ? wrl : wrh)
            + ((size_t)(g * H_ + j0 + jl)) * H_ + ch * 8;
        int c = ch >> 3, cc = ch & 7;
        int off = (hl ? LSM_WLO : LSM_WHI) + c * 8192
                + (int)SWZ128((uint32_t)(m * 128 + cc * 16));
        *(uint4*)(sm + off) = *(const uint4*)src;
    }

    // ---- zero h ping buffer 0 ----
    if (tid < 64)
        ((uint4*)g_hh0)[blockIdx.x * 64 + tid] = make_uint4(0, 0, 0, 0);
    group_barrier(bar);

    // per-warp MMA constants
    const int mf = wid & 3;              // gate
    const int kh = wid >> 2;             // k-half
    const int a_row = mf * 16 + (lane & 7) + ((lane >> 3) & 1) * 8;
    const int a_kb  = (lane >> 4) * 16;
    const int b_row = (lane & 7) + ((lane >> 4) & 1) * 8;
    const int b_kb  = ((lane >> 3) & 1) * 16;

    const int eb = tid & 31;
    const int ej = tid >> 5;
    float cst0 = 0.f, cst1 = 0.f;

    for (int t = 0; t < T_; ++t) {
        const __half* rh = (t & 1) ? g_hh1 : g_hh0;
        __half*      wh_ = (t & 1) ? g_hh0 : g_hh1;

        // ---- init acc from xg (kh=0) — LDG latency hidden behind staging ----
        float acc[4][4];
        if (kh == 0) {
            #pragma unroll
            for (int nf = 0; nf < 4; ++nf)
                #pragma unroll
                for (int q = 0; q < 4; ++q) {
                    int jl = (lane >> 2) + 8 * (q >> 1);
                    int bn = nf * 8 + 2 * (lane & 3) + (q & 1);
                    acc[nf][q] = __ldg(&xg[((size_t)t * G4H_ + mf * H_ + j0 + jl) * B_
                                           + b0 + bn]);
                }
        } else {
            #pragma unroll
            for (int nf = 0; nf < 4; ++nf)
                #pragma unroll
                for (int q = 0; q < 4; ++q) acc[nf][q] = 0.f;
        }

        // ---- stage h_prev (32 b x 512 k fp16 = 32 KB) ----
        #pragma unroll
        for (int i = 0; i < 8; ++i) {
            int id  = tid + i * 256;      // 0..2047
            int bl  = id >> 6;
            int ch  = id & 63;
            const __half* src = rh + (size_t)(b0 + bl) * H_ + ch * 8;
            int c = ch >> 3, cc = ch & 7;
            uint32_t dst = sb + LSM_HH + c * 4096
                         + SWZ128((uint32_t)(bl * 128 + cc * 16));
            CPASYNC16(dst, src);
        }
        CPCOMMIT();
        CPWAIT0();
        __syncthreads();

        // ---- MMA: 2 products (Whi*h + Wlo*h), 128 HMMA/warp ----
        #pragma unroll 4
        for (int kf = 0; kf < 16; ++kf) {
            int kfa = kh * 16 + kf;
            int c = kfa >> 2, ks = kfa & 3;
            uint32_t ah[4], al[4], bh[8];
            uint32_t aoff = sb + c * 8192
                          + SWZ128((uint32_t)(a_row * 128 + ks * 32 + a_kb));
            ldsm_x4(ah, aoff + LSM_WHI);
            ldsm_x4(al, aoff + LSM_WLO);
            #pragma unroll
            for (int nfp = 0; nfp < 2; ++nfp) {
                uint32_t boff = sb + LSM_HH + c * 4096
                    + SWZ128((uint32_t)((nfp * 16 + b_row) * 128 + ks * 32 + b_kb));
                ldsm_x4(bh + nfp * 4, boff);
            }
            #pragma unroll
            for (int nf = 0; nf < 4; ++nf) {
                mma16816(acc[nf], ah, bh + nf * 2);
                mma16816(acc[nf], al, bh + nf * 2);
            }
        }

        // ---- exchange partials via padded smem ----
        #pragma unroll
        for (int nf = 0; nf < 4; ++nf)
            #pragma unroll
            for (int q = 0; q < 4; ++q) {
                int m = (lane >> 2) + 8 * (q >> 1);
                int n = nf * 8 + 2 * (lane & 3) + (q & 1);
                redf[((kh * 4 + mf) * 16 + m) * 33 + n] = acc[nf][q];
            }
        __syncthreads();

        // ---- epilogue: 2 cells per thread ----
        #pragma unroll
        for (int cell = 0; cell < 2; ++cell) {
            int jl = ej + cell * 8;
            float pre[4];
            #pragma unroll
            for (int g = 0; g < 4; ++g) {
                pre[g] = redf[(g * 16 + jl) * 33 + eb]
                       + redf[((4 + g) * 16 + jl) * 33 + eb];
            }
            float ii = sigm_f(pre[0]), ff = sigm_f(pre[1]);
            float gg = tanh_f(pre[2]), oo = sigm_f(pre[3]);
            float& cc = cell ? cst1 : cst0;
            cc = ff * cc + ii * gg;
            float hv = oo * tanh_f(cc);
            __half hh = __float2half(hv);
            houth[eb * 16 + jl] = hh;
            if (hs_h)
                houtl[eb * 16 + jl] = __float2half(hv - __half2float(hh));
            if (t == T_ - 1)
                hfin[(size_t)(b0 + eb) * H_ + j0 + jl] = hv;
        }
        __syncthreads();

        // ---- publish h_t (fp16, 1 KB) ----
        if (tid < 64) {
            int bl = tid >> 1, p = tid & 1;
            *(uint4*)&wh_[(size_t)(b0 + bl) * H_ + j0 + p * 8] =
                *(uint4*)&houth[bl * 16 + p * 8];
        }
        __syncthreads();

        // ---- group barrier (release/acquire) with hs0 dump in the wait window ----
        unsigned int gen_ = 0;
        if (tid == 0) {
            asm volatile("ld.acquire.gpu.u32 %0, [%1];"
                         : "=r"(gen_) : "l"(bar + 1) : "memory");
            unsigned int arrived;
            asm volatile("atom.add.release.gpu.u32 %0, [%1], 1;"
                         : "=r"(arrived) : "l"(bar) : "memory");
            if (arrived == 31u) {
                asm volatile("st.relaxed.gpu.u32 [%0], 0;" :: "l"(bar) : "memory");
                asm volatile("red.add.release.gpu.u32 [%0], 1;" :: "l"(bar + 1) : "memory");
            }
        }
        if (hs_h && tid >= 128) {      // threads 128-255 dump while thread 0 waits
            int th = tid - 128;
            int bl = th >> 2, p = th & 3;
            size_t o2 = ((size_t)t * B_ + b0 + bl) * H_ + j0 + p * 4;
            *(uint2*)&hs_h[o2] = *(uint2*)&houth[bl * 16 + p * 4];
            *(uint2*)&hs_l[o2] = *(uint2*)&houtl[bl * 16 + p * 4];
        }
        if (tid == 0) {
            unsigned int g2;
            do {
                asm volatile("ld.acquire.gpu.u32 %0, [%1];"
                             : "=r"(g2) : "l"(bar + 1) : "memory");
            } while (g2 == gen_);
        }
        __syncthreads();
    }
}

// ---------------- fc head -----------------------------------------------------------
__global__ void fc_kernel(const float* __restrict__ h,
                          const float* __restrict__ W,
                          const float* __restrict__ bias,
                          float* __restrict__ out)
{
    int tid = threadIdx.x;
    int b = tid >> 1, o = tid & 1;
    float s = bias[o];
    const float* hp = h + (size_t)b * H_;
    const float* wp = W + (size_t)o * H_;
    for (int k = 0; k < H_; ++k) s = fmaf(hp[k], wp[k], s);
    out[b * OUT_ + o] = s;
}

// ---------------- launch -------------------------------------------------------------
extern "C" void kernel_launch(void* const* d_in, const int* in_sizes, int n_in,
                              void* d_out, int out_size)
{
    const float* x    = (const float*)d_in[0];
    const float* Wih0 = (const float*)d_in[1];
    const float* Whh0 = (const float*)d_in[2];
    const float* bih0 = (const float*)d_in[3];
    const float* bhh0 = (const float*)d_in[4];
    const float* Wih1 = (const float*)d_in[5];
    const float* Whh1 = (const float*)d_in[6];
    const float* bih1 = (const float*)d_in[7];
    const float* bhh1 = (const float*)d_in[8];
    const float* fcW  = (const float*)d_in[9];
    const float* fcb  = (const float*)d_in[10];
    float* out = (float*)d_out;

    float *xg, *hA;
    __half *xth, *xtl, *w0h, *w0l, *w1h, *w1l, *hs0h, *hs0l;
    __half *wr0h, *wr0l, *wr1h, *wr1l;
    cudaGetSymbolAddress((void**)&xg,   g_xg);
    cudaGetSymbolAddress((void**)&hA,   g_hA);
    cudaGetSymbolAddress((void**)&xth,  g_xth);
    cudaGetSymbolAddress((void**)&xtl,  g_xtl);
    cudaGetSymbolAddress((void**)&w0h,  g_w0h);
    cudaGetSymbolAddress((void**)&w0l,  g_w0l);
    cudaGetSymbolAddress((void**)&w1h,  g_w1h);
    cudaGetSymbolAddress((void**)&w1l,  g_w1l);
    cudaGetSymbolAddress((void**)&wr0h, g_wr0h);
    cudaGetSymbolAddress((void**)&wr0l, g_wr0l);
    cudaGetSymbolAddress((void**)&wr1h, g_wr1h);
    cudaGetSymbolAddress((void**)&wr1l, g_wr1l);
    cudaGetSymbolAddress((void**)&hs0h, g_hs0h);
    cudaGetSymbolAddress((void**)&hs0l, g_hs0l);

    cudaFuncSetAttribute(lstm_mma_kernel,
                         cudaFuncAttributeMaxDynamicSharedMemorySize, LSM_TOTAL);
    cudaFuncSetAttribute(gemm_mma_kernel,
                         cudaFuncAttributeMaxDynamicSharedMemorySize, GSM_TOTAL);

    // 1) transpose x -> fp16 hi/lo xt[t][b][d]
    transpose_kernel<<<dim3(T_ / 32, DIN_ / 32, B_), dim3(32, 8)>>>(x);

    // 2) split weights (input + recurrent)
    wsplit_kernel<<<(G4H_ * DIN_ + 255) / 256, 256>>>(Wih0, w0h, w0l, G4H_ * DIN_);
    wsplit_kernel<<<(G4H_ * H_   + 255) / 256, 256>>>(Wih1, w1h, w1l, G4H_ * H_);
    wsplit_kernel<<<(G4H_ * H_   + 255) / 256, 256>>>(Whh0, wr0h, wr0l, G4H_ * H_);
    wsplit_kernel<<<(G4H_ * H_   + 255) / 256, 256>>>(Whh1, wr1h, wr1l, G4H_ * H_);

    // 3) xg0 = xt @ Wih0^T + bias (fp16 3-product)
    gemm_mma_kernel<<<dim3(G4H_ / 128, T_), 256, GSM_TOTAL>>>(
        xth, xtl, w0h, w0l, bih0, bhh0, xg, DIN_);

    // 4) layer-0 recurrence (fp16 2-product; dumps hs0 fp16 hi/lo)
    lstm_mma_kernel<<<128, 256, LSM_TOTAL>>>(xg, wr0h, wr0l, hs0h, hs0l, hA);

    // 5) xg1 = hs0 @ Wih1^T + bias (fp16 3-product)
    gemm_mma_kernel<<<dim3(G4H_ / 128, T_), 256, GSM_TOTAL>>>(
        hs0h, hs0l, w1h, w1l, bih1, bhh1, xg, H_);

    // 6) layer-1 recurrence (final fp32 h -> hA)
    lstm_mma_kernel<<<128, 256, LSM_TOTAL>>>(xg, wr1h, wr1l,
                                             (__half*)0, (__half*)0, hA);

    // 7) fc head
    fc_kernel<<<1, 256>>>(hA, fcW, fcb, out);
}

// round 9
// speedup vs baseline: 15.2609x; 1.7952x over previous
#include <cuda_runtime.h>
#include <cuda_fp16.h>
#include <math.h>
#include <stdint.h>
#include <stddef.h>

#define B_   128
#define DIN_ 128
#define T_   1024
#define H_   512
#define G4H_ 2048
#define OUT_ 2

// ---------------- scratch (static device allocations; no cudaMalloc) ----------------
__device__ __half g_xth [(size_t)T_ * B_ * DIN_];  // x transposed, fp16 hi
__device__ __half g_xtl [(size_t)T_ * B_ * DIN_];  // fp16 lo residual
__device__ __half g_w0h [(size_t)G4H_ * DIN_];     // Wih0 hi/lo (GEMM1, 3-product)
__device__ __half g_w0l [(size_t)G4H_ * DIN_];
__device__ __half g_wr0 [(size_t)G4H_ * H_];       // Whh0 fp16 single
__device__ __half g_wr1 [(size_t)G4H_ * H_];       // Whh1 fp16 single
__device__ __half g_wi1 [(size_t)G4H_ * H_];       // Wih1 fp16 single
__device__ __half g_h0a [B_ * H_];                 // h0 ping-pong
__device__ __half g_h0b [B_ * H_];
__device__ __half g_h1a [B_ * H_];                 // h1 ping-pong
__device__ __half g_h1b [B_ * H_];
__device__ float g_xg [(size_t)T_ * G4H_ * B_];    // layer-0 gate preacts [t][n][b]
__device__ float g_hA [B_ * H_];                   // final h1 fp32 for fc
__device__ unsigned int g_bar[4 * 32];

// ---------------- small helpers -----------------------------------------------------
__device__ __forceinline__ void hsplit(float v, __half& h, __half& l) {
    h = __float2half(v);
    l = __float2half(v - __half2float(h));
}
__device__ __forceinline__ uint32_t smem_u32(const void* p) {
    uint32_t a;
    asm("{ .reg .u64 t; cvta.to.shared.u64 t, %1; cvt.u32.u64 %0, t; }" : "=r"(a) : "l"(p));
    return a;
}
#define SWZ128(o) ((o) ^ (((o) >> 3) & 0x70))

__device__ __forceinline__ void ldsm_x4(uint32_t* r, uint32_t addr) {
    asm volatile("ldmatrix.sync.aligned.m8n8.x4.shared.b16 {%0,%1,%2,%3}, [%4];"
        : "=r"(r[0]), "=r"(r[1]), "=r"(r[2]), "=r"(r[3]) : "r"(addr));
}
__device__ __forceinline__ void mma16816(float* d, const uint32_t* a, const uint32_t* b) {
    asm volatile("mma.sync.aligned.m16n8k16.row.col.f32.f16.f16.f32 "
        "{%0,%1,%2,%3}, {%4,%5,%6,%7}, {%8,%9}, {%0,%1,%2,%3};"
        : "+f"(d[0]), "+f"(d[1]), "+f"(d[2]), "+f"(d[3])
        : "r"(a[0]), "r"(a[1]), "r"(a[2]), "r"(a[3]), "r"(b[0]), "r"(b[1]));
}
#define CPASYNC16(dst, src) \
    asm volatile("cp.async.cg.shared.global [%0], [%1], 16;" :: "r"(dst), "l"(src))
#define CPCOMMIT() asm volatile("cp.async.commit_group;" ::: "memory")
#define CPWAIT0()  asm volatile("cp.async.wait_group 0;" ::: "memory")
#define CPWAIT1()  asm volatile("cp.async.wait_group 1;" ::: "memory")

// ---------------- per-b-group barrier (32 CTAs), release/acquire ---------------------
__device__ __forceinline__ void group_barrier(unsigned int* bar) {
    __syncthreads();
    if (threadIdx.x == 0) {
        unsigned int gen;
        asm volatile("ld.acquire.gpu.u32 %0, [%1];" : "=r"(gen) : "l"(bar + 1) : "memory");
        unsigned int arrived;
        asm volatile("atom.add.release.gpu.u32 %0, [%1], 1;"
                     : "=r"(arrived) : "l"(bar) : "memory");
        if (arrived == 31u) {
            asm volatile("st.relaxed.gpu.u32 [%0], 0;" :: "l"(bar) : "memory");
            asm volatile("red.add.release.gpu.u32 [%0], 1;" :: "l"(bar + 1) : "memory");
        } else {
            unsigned int g2;
            do {
                asm volatile("ld.acquire.gpu.u32 %0, [%1];"
                             : "=r"(g2) : "l"(bar + 1) : "memory");
            } while (g2 == gen);
        }
    }
    __syncthreads();
}

// ---------------- transpose x: (B, D, T) -> xt[t][b][d] as fp16 hi/lo ----------------
__global__ void transpose_kernel(const float* __restrict__ x) {
    __shared__ float tile[32][33];
    const int b  = blockIdx.z;
    const int t0 = blockIdx.x * 32;
    const int d0 = blockIdx.y * 32;
    const int tx = threadIdx.x, ty = threadIdx.y;
    #pragma unroll
    for (int i = 0; i < 4; ++i) {
        int d = d0 + ty + i * 8;
        tile[ty + i * 8][tx] = x[((size_t)b * DIN_ + d) * T_ + t0 + tx];
    }
    __syncthreads();
    #pragma unroll
    for (int i = 0; i < 4; ++i) {
        int t = t0 + ty + i * 8;
        float v = tile[tx][ty + i * 8];
        __half h, l;
        hsplit(v, h, l);
        size_t idx = ((size_t)t * B_ + b) * DIN_ + d0 + tx;
        g_xth[idx] = h;
        g_xtl[idx] = l;
    }
}

// ---------------- weight prep -------------------------------------------------------
__global__ void wsplit_kernel(const float* __restrict__ w,
                              __half* __restrict__ wh,
                              __half* __restrict__ wl, int n) {
    int i = blockIdx.x * blockDim.x + threadIdx.x;
    if (i < n) {
        __half h, l;
        hsplit(w[i], h, l);
        wh[i] = h;
        wl[i] = l;
    }
}
__global__ void wconv_kernel(const float* __restrict__ w,
                             __half* __restrict__ wh, int n) {
    int i = blockIdx.x * blockDim.x + threadIdx.x;
    if (i < n) wh[i] = __float2half(w[i]);
}

// ---------------- mma.sync split-fp16 GEMM (3-product; xg0 anchor) -------------------
#define TILE_BYTES  16384
#define STAGE_BYTES (4 * TILE_BYTES)
#define GSM_TOTAL   (2 * STAGE_BYTES)

__global__ void __launch_bounds__(256, 1)
gemm_mma_kernel(const __half* __restrict__ Ah, const __half* __restrict__ Al,
                const __half* __restrict__ Bh, const __half* __restrict__ Bl,
                const float* __restrict__ bias1, const float* __restrict__ bias2,
                float* __restrict__ C, int K)
{
    extern __shared__ char smem[];
    const uint32_t sb = smem_u32(smem);
    const int tid  = threadIdx.x;
    const int lane = tid & 31;
    const int warp = tid >> 5;
    const int tile_t = blockIdx.y;
    const int n0blk  = blockIdx.x * 128;
    const int m_off = (warp & 3) * 32;
    const int n_off = (warp >> 2) * 64;

    const __half* gsrc[4] = {
        Ah + (size_t)tile_t * 128 * K, Al + (size_t)tile_t * 128 * K,
        Bh + (size_t)n0blk * K,        Bl + (size_t)n0blk * K };

    auto issue_stage = [&](int buf, int kc) {
        #pragma unroll
        for (int i = 0; i < 16; ++i) {
            int id  = tid + i * 256;
            int tl  = id >> 10;
            int rem = id & 1023;
            int row = rem >> 3;
            int ch  = rem & 7;
            const __half* src = gsrc[tl] + (size_t)row * K + kc * 64 + ch * 8;
            uint32_t dst = sb + buf * STAGE_BYTES + tl * TILE_BYTES
                         + SWZ128((uint32_t)(row * 128 + ch * 16));
            CPASYNC16(dst, src);
        }
        CPCOMMIT();
    };

    float acc[2][8][4];
    #pragma unroll
    for (int mf = 0; mf < 2; ++mf)
        #pragma unroll
        for (int nf = 0; nf < 8; ++nf)
            #pragma unroll
            for (int r = 0; r < 4; ++r) acc[mf][nf][r] = 0.f;

    const int nkc = K >> 6;
    issue_stage(0, 0);
    issue_stage(1, 1);

    const int a_row_base = (lane & 7) + ((lane >> 3) & 1) * 8;
    const int a_kh       = (lane >> 4) * 16;
    const int b_row_base = (lane & 7) + ((lane >> 4) & 1) * 8;
    const int b_kh       = ((lane >> 3) & 1) * 16;

    for (int kc = 0; kc < nkc; ++kc) {
        if (kc + 1 < nkc) { CPWAIT1(); } else { CPWAIT0(); }
        __syncthreads();

        const uint32_t st = sb + (kc & 1) * STAGE_BYTES;
        #pragma unroll
        for (int ks = 0; ks < 4; ++ks) {
            uint32_t ah[2][4], al[2][4], bh[16], bl[16];
            #pragma unroll
            for (int mf = 0; mf < 2; ++mf) {
                uint32_t off = SWZ128((uint32_t)((m_off + mf * 16 + a_row_base) * 128
                                                 + ks * 32 + a_kh));
                ldsm_x4(ah[mf], st + 0 * TILE_BYTES + off);
                ldsm_x4(al[mf], st + 1 * TILE_BYTES + off);
            }
            #pragma unroll
            for (int bf = 0; bf < 4; ++bf) {
                uint32_t off = SWZ128((uint32_t)((n_off + bf * 16 + b_row_base) * 128
                                                 + ks * 32 + b_kh));
                ldsm_x4(bh + bf * 4, st + 2 * TILE_BYTES + off);
                ldsm_x4(bl + bf * 4, st + 3 * TILE_BYTES + off);
            }
            #pragma unroll
            for (int mf = 0; mf < 2; ++mf)
                #pragma unroll
                for (int nf = 0; nf < 8; ++nf) {
                    mma16816(acc[mf][nf], ah[mf], bh + nf * 2);
                    mma16816(acc[mf][nf], ah[mf], bl + nf * 2);
                    mma16816(acc[mf][nf], al[mf], bh + nf * 2);
                }
        }
        __syncthreads();
        if (kc + 2 < nkc) issue_stage(kc & 1, kc + 2);
    }

    #pragma unroll
    for (int nf = 0; nf < 8; ++nf) {
        int n = n0blk + n_off + nf * 8 + 2 * (lane & 3);
        float bv0 = __ldg(&bias1[n])     + __ldg(&bias2[n]);
        float bv1 = __ldg(&bias1[n + 1]) + __ldg(&bias2[n + 1]);
        #pragma unroll
        for (int mf = 0; mf < 2; ++mf) {
            int b = m_off + mf * 16 + (lane >> 2);
            float* c0 = &C[((size_t)tile_t * G4H_ + n) * B_ + b];
            c0[0]       = acc[mf][nf][0] + bv0;
            c0[B_]      = acc[mf][nf][1] + bv1;
            c0[8]       = acc[mf][nf][2] + bv0;
            c0[B_ + 8]  = acc[mf][nf][3] + bv1;
        }
    }
}

// ---------------- fused dual-layer persistent LSTM recurrence ------------------------
// 128 CTAs = 4 b-groups (32 b) x 32 j-tiles (16 j). 256 threads.
// Super-step t: layer-0 h0[t] (xg0 preloaded) AND layer-1 h1[t-1]
// (acc1 = bias1 + Wih1@h0[t-1] + Whh1@h1[t-2], all tensor-core, 1-step pipeline).
// Whh0/Whh1 fp16 resident in smem; Wih1 A-fragments resident in REGISTERS.
#define LSM_W0   0                      // Whh0: 8 chunks x 8192 = 64 KB
#define LSM_W1   65536                  // Whh1: 64 KB
#define LSM_H0   131072                 // h0 tile 32 KB (init: Wih1 temp, 64 KB w/ H1)
#define LSM_H1   163840                 // h1 tile 32 KB
#define LSM_RED  196608                 // 2 kh x 4 g x 16 m x 33 n x 4B = 16896
#define LSM_HO0  213504                 // 32 x 16 fp16 = 1 KB
#define LSM_HO1  214528
#define LSM_TOTAL 215552

__device__ __forceinline__ float sigm_f(float v) {
    return __fdividef(1.f, 1.f + __expf(-v));
}
__device__ __forceinline__ float tanh_f(float v) {
    return 1.f - __fdividef(2.f, __expf(2.f * v) + 1.f);
}

__global__ void __launch_bounds__(256, 1)
lstm_fused_kernel(const float* __restrict__ xg,      // [t][n][b] (layer-0 preacts)
                  const __half* __restrict__ whh0,
                  const __half* __restrict__ whh1,
                  const __half* __restrict__ wih1,
                  const float* __restrict__ bih1,
                  const float* __restrict__ bhh1,
                  float* __restrict__ hfin)          // final fp32 h1
{
    extern __shared__ char sm[];
    const uint32_t sb = smem_u32(sm);
    float* redf = (float*)(sm + LSM_RED);
    __half* hout0 = (__half*)(sm + LSM_HO0);
    __half* hout1 = (__half*)(sm + LSM_HO1);

    const int tid  = threadIdx.x;
    const int lane = tid & 31;
    const int wid  = tid >> 5;
    const int grp  = blockIdx.x & 3;
    const int jt   = blockIdx.x >> 2;
    const int b0   = grp * 32;
    const int j0   = jt * 16;
    unsigned int* bar = g_bar + grp * 32;

    const int mf = wid & 3;              // gate
    const int kh = wid >> 2;             // k-half
    const int a_row = mf * 16 + (lane & 7) + ((lane >> 3) & 1) * 8;
    const int a_kb  = (lane >> 4) * 16;
    const int b_row = (lane & 7) + ((lane >> 4) & 1) * 8;
    const int b_kb  = ((lane >> 3) & 1) * 16;

    // ---- stage Whh0 -> LSM_W0, Whh1 -> LSM_W1, Wih1 -> temp (LSM_H0, 64 KB) ----
    #pragma unroll
    for (int i = 0; i < 16; ++i) {
        int id = tid + i * 256;           // 0..4095 16B-chunks
        int m  = id >> 6, ch = id & 63;
        int g = m >> 4, jl = m & 15;
        size_t roff = ((size_t)(g * H_ + j0 + jl)) * H_ + ch * 8;
        int c = ch >> 3, cc = ch & 7;
        uint32_t soff = c * 8192 + SWZ128((uint32_t)(m * 128 + cc * 16));
        *(uint4*)(sm + LSM_W0 + soff) = *(const uint4*)(whh0 + roff);
        *(uint4*)(sm + LSM_W1 + soff) = *(const uint4*)(whh1 + roff);
        *(uint4*)(sm + LSM_H0 + soff) = *(const uint4*)(wih1 + roff);
    }

    // ---- zero edge h buffers (read at t=0 / t=1) ----
    if (tid < 64) {
        int bl = tid >> 1, p = tid & 1;
        size_t o = (size_t)(b0 + bl) * H_ + j0 + p * 8;
        *(uint4*)&g_h0b[o] = make_uint4(0, 0, 0, 0);
        *(uint4*)&g_h1b[o] = make_uint4(0, 0, 0, 0);
    }
    __syncthreads();

    // ---- Wih1 A-fragments -> registers (persist whole kernel) ----
    uint32_t wi1f[64];
    #pragma unroll
    for (int kf = 0; kf < 16; ++kf) {
        int kfa = kh * 16 + kf;
        int c = kfa >> 2, ks = kfa & 3;
        ldsm_x4(&wi1f[kf * 4],
                sb + LSM_H0 + c * 8192 + SWZ128((uint32_t)(a_row * 128 + ks * 32 + a_kb)));
    }

    // ---- layer-1 bias (per-thread, rows m_lo / m_hi of this warp's gate) ----
    const int m_lo = lane >> 2;
    float bias_lo = __ldg(&bih1[mf * H_ + j0 + m_lo])     + __ldg(&bhh1[mf * H_ + j0 + m_lo]);
    float bias_hi = __ldg(&bih1[mf * H_ + j0 + m_lo + 8]) + __ldg(&bhh1[mf * H_ + j0 + m_lo + 8]);

    group_barrier(bar);

    const int eb = tid & 31;
    const int ej = tid >> 5;
    float c0a = 0.f, c0b = 0.f;   // layer-0 cell states
    float c1a = 0.f, c1b = 0.f;   // layer-1 cell states

    for (int t = 0; t <= T_; ++t) {
        // ping-pong: read h0[t-1] / h1[t-2]; write h0[t] / h1[t-1]
        const __half* r0 = (t & 1) ? g_h0a : g_h0b;
        __half*       w0 = (t & 1) ? g_h0b : g_h0a;
        const __half* r1 = (t & 1) ? g_h1b : g_h1a;
        __half*       w1 = (t & 1) ? g_h1a : g_h1b;

        // ---- acc init: layer-0 from xg0[t] (kh=0), layer-1 from bias (kh=0) ----
        float acc0[4][4], acc1[4][4];
        if (kh == 0) {
            if (t < T_) {
                #pragma unroll
                for (int nf = 0; nf < 4; ++nf)
                    #pragma unroll
                    for (int q = 0; q < 4; ++q) {
                        int jl = (lane >> 2) + 8 * (q >> 1);
                        int bn = nf * 8 + 2 * (lane & 3) + (q & 1);
                        acc0[nf][q] = __ldg(&xg[((size_t)t * G4H_ + mf * H_ + j0 + jl) * B_
                                                + b0 + bn]);
                    }
            } else {
                #pragma unroll
                for (int nf = 0; nf < 4; ++nf)
                    #pragma unroll
                    for (int q = 0; q < 4; ++q) acc0[nf][q] = 0.f;
            }
            #pragma unroll
            for (int nf = 0; nf < 4; ++nf)
                #pragma unroll
                for (int q = 0; q < 4; ++q)
                    acc1[nf][q] = (q & 2) ? bias_hi : bias_lo;
        } else {
            #pragma unroll
            for (int nf = 0; nf < 4; ++nf)
                #pragma unroll
                for (int q = 0; q < 4; ++q) { acc0[nf][q] = 0.f; acc1[nf][q] = 0.f; }
        }

        // ---- stage h0[t-1] and h1[t-2] tiles (32 KB each) ----
        #pragma unroll
        for (int i = 0; i < 8; ++i) {
            int id = tid + i * 256;       // 0..2047
            int bl = id >> 6, ch = id & 63;
            int c = ch >> 3, cc = ch & 7;
            uint32_t soff = c * 4096 + SWZ128((uint32_t)(bl * 128 + cc * 16));
            CPASYNC16(sb + LSM_H0 + soff, r0 + (size_t)(b0 + bl) * H_ + ch * 8);
            CPASYNC16(sb + LSM_H1 + soff, r1 + (size_t)(b0 + bl) * H_ + ch * 8);
        }
        CPCOMMIT();
        CPWAIT0();
        __syncthreads();

        // ---- MMA: acc0 += Whh0@h0 ; acc1 += Wih1@h0 + Whh1@h1 ----
        #pragma unroll
        for (int kf = 0; kf < 16; ++kf) {
            int kfa = kh * 16 + kf;
            int c = kfa >> 2, ks = kfa & 3;
            uint32_t a0[4], a1[4], b0f[8], b1f[8];
            uint32_t arow = SWZ128((uint32_t)(a_row * 128 + ks * 32 + a_kb));
            ldsm_x4(a0, sb + LSM_W0 + c * 8192 + arow);
            ldsm_x4(a1, sb + LSM_W1 + c * 8192 + arow);
            #pragma unroll
            for (int nfp = 0; nfp < 2; ++nfp) {
                uint32_t bo = SWZ128((uint32_t)((nfp * 16 + b_row) * 128 + ks * 32 + b_kb));
                ldsm_x4(b0f + nfp * 4, sb + LSM_H0 + c * 4096 + bo);
                ldsm_x4(b1f + nfp * 4, sb + LSM_H1 + c * 4096 + bo);
            }
            #pragma unroll
            for (int nf = 0; nf < 4; ++nf) {
                mma16816(acc0[nf], a0, b0f + nf * 2);
                mma16816(acc1[nf], &wi1f[kf * 4], b0f + nf * 2);
                mma16816(acc1[nf], a1, b1f + nf * 2);
            }
        }

        // ---- layer-0 exchange + epilogue (t < T) ----
        if (t < T_) {
            #pragma unroll
            for (int nf = 0; nf < 4; ++nf)
                #pragma unroll
                for (int q = 0; q < 4; ++q) {
                    int m = (lane >> 2) + 8 * (q >> 1);
                    int n = nf * 8 + 2 * (lane & 3) + (q & 1);
                    redf[((kh * 4 + mf) * 16 + m) * 33 + n] = acc0[nf][q];
                }
            __syncthreads();
            #pragma unroll
            for (int cell = 0; cell < 2; ++cell) {
                int jl = ej + cell * 8;
                float pre[4];
                #pragma unroll
                for (int g = 0; g < 4; ++g)
                    pre[g] = redf[(g * 16 + jl) * 33 + eb]
                           + redf[((4 + g) * 16 + jl) * 33 + eb];
                float ii = sigm_f(pre[0]), ff = sigm_f(pre[1]);
                float gg = tanh_f(pre[2]), oo = sigm_f(pre[3]);
                float& cc = cell ? c0b : c0a;
                cc = ff * cc + ii * gg;
                hout0[eb * 16 + jl] = __float2half(oo * tanh_f(cc));
            }
            __syncthreads();   // red reuse
        }

        // ---- layer-1 exchange + epilogue (t >= 1), computes h1[t-1] ----
        if (t >= 1) {
            #pragma unroll
            for (int nf = 0; nf < 4; ++nf)
                #pragma unroll
                for (int q = 0; q < 4; ++q) {
                    int m = (lane >> 2) + 8 * (q >> 1);
                    int n = nf * 8 + 2 * (lane & 3) + (q & 1);
                    redf[((kh * 4 + mf) * 16 + m) * 33 + n] = acc1[nf][q];
                }
            __syncthreads();
            #pragma unroll
            for (int cell = 0; cell < 2; ++cell) {
                int jl = ej + cell * 8;
                float pre[4];
                #pragma unroll
                for (int g = 0; g < 4; ++g)
                    pre[g] = redf[(g * 16 + jl) * 33 + eb]
                           + redf[((4 + g) * 16 + jl) * 33 + eb];
                float ii = sigm_f(pre[0]), ff = sigm_f(pre[1]);
                float gg = tanh_f(pre[2]), oo = sigm_f(pre[3]);
                float& cc = cell ? c1b : c1a;
                cc = ff * cc + ii * gg;
                float hv = oo * tanh_f(cc);
                hout1[eb * 16 + jl] = __float2half(hv);
                if (t == T_)
                    hfin[(size_t)(b0 + eb) * H_ + j0 + jl] = hv;
            }
        }
        __syncthreads();

        // ---- publish h0[t] (threads 0-63) and h1[t-1] (threads 64-127) ----
        if (t < T_ && tid < 64) {
            int bl = tid >> 1, p = tid & 1;
            *(uint4*)&w0[(size_t)(b0 + bl) * H_ + j0 + p * 8] =
                *(uint4*)&hout0[bl * 16 + p * 8];
        }
        if (t >= 1 && t < T_ && tid >= 64 && tid < 128) {
            int th = tid - 64;
            int bl = th >> 1, p = th & 1;
            *(uint4*)&w1[(size_t)(b0 + bl) * H_ + j0 + p * 8] =
                *(uint4*)&hout1[bl * 16 + p * 8];
        }

        if (t < T_) group_barrier(bar);
    }
}

// ---------------- fc head -----------------------------------------------------------
__global__ void fc_kernel(const float* __restrict__ h,
                          const float* __restrict__ W,
                          const float* __restrict__ bias,
                          float* __restrict__ out)
{
    int tid = threadIdx.x;
    int b = tid >> 1, o = tid & 1;
    float s = bias[o];
    const float* hp = h + (size_t)b * H_;
    const float* wp = W + (size_t)o * H_;
    for (int k = 0; k < H_; ++k) s = fmaf(hp[k], wp[k], s);
    out[b * OUT_ + o] = s;
}

// ---------------- launch -------------------------------------------------------------
extern "C" void kernel_launch(void* const* d_in, const int* in_sizes, int n_in,
                              void* d_out, int out_size)
{
    const float* x    = (const float*)d_in[0];
    const float* Wih0 = (const float*)d_in[1];
    const float* Whh0 = (const float*)d_in[2];
    const float* bih0 = (const float*)d_in[3];
    const float* bhh0 = (const float*)d_in[4];
    const float* Wih1 = (const float*)d_in[5];
    const float* Whh1 = (const float*)d_in[6];
    const float* bih1 = (const float*)d_in[7];
    const float* bhh1 = (const float*)d_in[8];
    const float* fcW  = (const float*)d_in[9];
    const float* fcb  = (const float*)d_in[10];
    float* out = (float*)d_out;

    float *xg, *hA;
    __half *xth, *xtl, *w0h, *w0l, *wr0, *wr1, *wi1;
    cudaGetSymbolAddress((void**)&xg,  g_xg);
    cudaGetSymbolAddress((void**)&hA,  g_hA);
    cudaGetSymbolAddress((void**)&xth, g_xth);
    cudaGetSymbolAddress((void**)&xtl, g_xtl);
    cudaGetSymbolAddress((void**)&w0h, g_w0h);
    cudaGetSymbolAddress((void**)&w0l, g_w0l);
    cudaGetSymbolAddress((void**)&wr0, g_wr0);
    cudaGetSymbolAddress((void**)&wr1, g_wr1);
    cudaGetSymbolAddress((void**)&wi1, g_wi1);

    cudaFuncSetAttribute(lstm_fused_kernel,
                         cudaFuncAttributeMaxDynamicSharedMemorySize, LSM_TOTAL);
    cudaFuncSetAttribute(gemm_mma_kernel,
                         cudaFuncAttributeMaxDynamicSharedMemorySize, GSM_TOTAL);

    // 1) transpose x -> fp16 hi/lo xt[t][b][d]
    transpose_kernel<<<dim3(T_ / 32, DIN_ / 32, B_), dim3(32, 8)>>>(x);

    // 2) weight prep: Wih0 hi/lo (GEMM1); Whh0/Whh1/Wih1 single fp16 (fused kernel)
    wsplit_kernel<<<(G4H_ * DIN_ + 255) / 256, 256>>>(Wih0, w0h, w0l, G4H_ * DIN_);
    wconv_kernel<<<(G4H_ * H_ + 255) / 256, 256>>>(Whh0, wr0, G4H_ * H_);
    wconv_kernel<<<(G4H_ * H_ + 255) / 256, 256>>>(Whh1, wr1, G4H_ * H_);
    wconv_kernel<<<(G4H_ * H_ + 255) / 256, 256>>>(Wih1, wi1, G4H_ * H_);

    // 3) xg0 = xt @ Wih0^T + bias (fp16 3-product, precision anchor)
    gemm_mma_kernel<<<dim3(G4H_ / 128, T_), 256, GSM_TOTAL>>>(
        xth, xtl, w0h, w0l, bih0, bhh0, xg, DIN_);

    // 4) fused dual-layer recurrence (layer-1 lags layer-0 by one step)
    lstm_fused_kernel<<<128, 256, LSM_TOTAL>>>(xg, wr0, wr1, wi1, bih1, bhh1, hA);

    // 5) fc head
    fc_kernel<<<1, 256>>>(hA, fcW, fcb, out);
}